// round 1
// baseline (speedup 1.0000x reference)
#include <cuda_runtime.h>

// Problem constants
#define D_MODEL   1024
#define NUM_HEADS 16
#define DEPTH     64
#define BATCH     2
#define SEQ       2048
#define BH        (BATCH*NUM_HEADS)     // 32
#define M_ROWS    (BATCH*SEQ)           // 4096

// -------- device scratch (allocation-free workaround) --------
__device__ float g_qh[BH*SEQ*DEPTH];     // [B,H,S,d] 16MB
__device__ float g_kh[BH*SEQ*DEPTH];
__device__ float g_vh[BH*SEQ*DEPTH];
__device__ float g_ctx[M_ROWS*D_MODEL];  // [B,S,D] pre-Wo context

// ============================================================
// Tiled fp32 GEMM: Y = X[M,K] @ W[K,N] + bias[N]
// mode 0/1/2: X=Xext, Y = g_qh/g_kh/g_vh with head-split layout [B,H,S,d]
// mode 3    : X=g_ctx, Y=Yext linear [M,N]
// Block: 256 threads, 64x64 tile, 4x4 per-thread microtile, BK=16.
// ============================================================
__global__ void gemm64(const float* __restrict__ Xext,
                       const float* __restrict__ W,
                       const float* __restrict__ bias,
                       float* __restrict__ Yext,
                       int mode)
{
    const int K = D_MODEL, N = D_MODEL;
    const float* X = (mode == 3) ? g_ctx : Xext;
    float* Y;
    if      (mode == 0) Y = g_qh;
    else if (mode == 1) Y = g_kh;
    else if (mode == 2) Y = g_vh;
    else                Y = Yext;

    __shared__ float As[16][65];   // padded to avoid STS conflicts
    __shared__ float Bs[16][64];

    const int tid = threadIdx.x;
    const int tx = tid & 15;        // 0..15 (col group)
    const int ty = tid >> 4;        // 0..15 (row group)
    const int row0 = blockIdx.y * 64;
    const int col0 = blockIdx.x * 64;

    float acc[4][4];
#pragma unroll
    for (int i = 0; i < 4; i++)
#pragma unroll
        for (int j = 0; j < 4; j++) acc[i][j] = 0.f;

    for (int k0 = 0; k0 < K; k0 += 16) {
        // load A tile (64 rows x 16 k), coalesced over k within a row
#pragma unroll
        for (int it = 0; it < 4; it++) {
            int m = (tid >> 4) + it * 16;
            int k = tid & 15;
            As[k][m] = X[(size_t)(row0 + m) * K + k0 + k];
        }
        // load B tile (16 k x 64 cols), coalesced over cols
#pragma unroll
        for (int it = 0; it < 4; it++) {
            int k = (tid >> 6) + it * 4;
            int n = tid & 63;
            Bs[k][n] = W[(size_t)(k0 + k) * N + col0 + n];
        }
        __syncthreads();

#pragma unroll
        for (int k = 0; k < 16; k++) {
            float a[4], b[4];
#pragma unroll
            for (int i = 0; i < 4; i++) a[i] = As[k][ty * 4 + i];
#pragma unroll
            for (int j = 0; j < 4; j++) b[j] = Bs[k][tx * 4 + j];
#pragma unroll
            for (int i = 0; i < 4; i++)
#pragma unroll
                for (int j = 0; j < 4; j++)
                    acc[i][j] += a[i] * b[j];
        }
        __syncthreads();
    }

    // epilogue
#pragma unroll
    for (int i = 0; i < 4; i++) {
        int r = row0 + ty * 4 + i;
#pragma unroll
        for (int j = 0; j < 4; j++) {
            int c = col0 + tx * 4 + j;
            float v = acc[i][j] + bias[c];
            if (mode <= 2) {
                // head-split: row r = b*SEQ + s ; col c = h*DEPTH + dd
                int b_ = r >> 11;           // SEQ = 2048
                int s_ = r & (SEQ - 1);
                int h  = c >> 6;            // DEPTH = 64
                int dd = c & 63;
                Y[(size_t)(((b_ << 4) + h) * SEQ + s_) * DEPTH + dd] = v;
            } else {
                Y[(size_t)r * D_MODEL + c] = v;
            }
        }
    }
}

// ============================================================
// Attention: one block (128 threads) per (query row i, batch*head bh).
// Scores for the whole row live in smem; block-wide softmax; then P@V.
// Optionally writes the full attn probability row.
// ============================================================
__global__ void attn_row(const unsigned char* __restrict__ mask,
                         float* __restrict__ attn_out, int writeAttn)
{
    __shared__ __align__(16) float sc[SEQ];     // 8KB scores
    __shared__ __align__(16) float qs[DEPTH];
    __shared__ float red[128];

    const int i   = blockIdx.x;
    const int bh  = blockIdx.y;
    const int b_  = bh >> 4;
    const int tid = threadIdx.x;

    const float* qrow = g_qh + ((size_t)bh * SEQ + i) * DEPTH;
    const float* kb   = g_kh + (size_t)bh * SEQ * DEPTH;
    const float* vb   = g_vh + (size_t)bh * SEQ * DEPTH;

    if (tid < DEPTH) qs[tid] = qrow[tid];
    __syncthreads();

    const float scale = 0.125f;   // 1/sqrt(64)
    const unsigned char* mrow = mask + ((size_t)b_ * SEQ + i) * SEQ;

    // pass 1: scores + local max
    float lmax = -3.4e38f;
    for (int j = tid; j < SEQ; j += 128) {
        float s;
        if (j <= i && !mrow[j]) {
            const float4* kr = (const float4*)(kb + (size_t)j * DEPTH);
            float dot = 0.f;
#pragma unroll
            for (int d4 = 0; d4 < 16; d4++) {
                float4 kv = kr[d4];
                float4 qv = *(const float4*)(qs + d4 * 4);
                dot += qv.x * kv.x + qv.y * kv.y + qv.z * kv.z + qv.w * kv.w;
            }
            s = dot * scale + (float)(j - i);   // RPE bias j-i
        } else {
            s = -1e9f;                           // padding or causal mask
        }
        sc[j] = s;
        lmax = fmaxf(lmax, s);
    }

    // block-reduce max
    red[tid] = lmax;
    __syncthreads();
    for (int off = 64; off > 0; off >>= 1) {
        if (tid < off) red[tid] = fmaxf(red[tid], red[tid + off]);
        __syncthreads();
    }
    const float m = red[0];
    __syncthreads();

    // pass 2: exp + local sum
    float lsum = 0.f;
    for (int j = tid; j < SEQ; j += 128) {
        float p = __expf(sc[j] - m);   // masked entries underflow to exactly 0
        sc[j] = p;
        lsum += p;
    }
    red[tid] = lsum;
    __syncthreads();
    for (int off = 64; off > 0; off >>= 1) {
        if (tid < off) red[tid] = red[tid] + red[tid + off];
        __syncthreads();
    }
    const float inv = 1.0f / red[0];
    __syncthreads();

    if (writeAttn) {
        float* arow = attn_out + ((size_t)bh * SEQ + i) * SEQ;
        for (int j = tid; j < SEQ; j += 128) arow[j] = sc[j] * inv;
    }

    // out_dd = sum_j p_j * V[j,dd]  (two threads per dd split the j range)
    const int dd   = tid & 63;
    const int half = tid >> 6;
    float acc = 0.f;
    for (int j = half; j <= i; j += 2)
        acc += sc[j] * vb[(size_t)j * DEPTH + dd];
    red[tid] = acc;
    __syncthreads();
    if (tid < 64) {
        int h = bh & 15;
        g_ctx[((size_t)(b_ * SEQ + i)) * D_MODEL + h * DEPTH + tid] =
            (red[tid] + red[tid + 64]) * inv;
    }
}

// ============================================================
extern "C" void kernel_launch(void* const* d_in, const int* in_sizes, int n_in,
                              void* d_out, int out_size)
{
    const float* q  = (const float*)d_in[0];
    const float* k  = (const float*)d_in[1];
    const float* v  = (const float*)d_in[2];
    const float* Wq = (const float*)d_in[3];
    const float* bq = (const float*)d_in[4];
    const float* Wk = (const float*)d_in[5];
    const float* bk = (const float*)d_in[6];
    const float* Wv = (const float*)d_in[7];
    const float* bv = (const float*)d_in[8];
    const float* Wo = (const float*)d_in[9];
    const float* bo = (const float*)d_in[10];
    const unsigned char* mask = (const unsigned char*)d_in[11];

    float* out = (float*)d_out;
    const long long OUT_ELEMS = (long long)BATCH * SEQ * D_MODEL;  // 4,194,304
    const int writeAttn = ((long long)out_size > OUT_ELEMS) ? 1 : 0;
    float* attn_out = out + OUT_ELEMS;   // tuple order: (out, attn)

    dim3 gg(D_MODEL / 64, M_ROWS / 64);  // (16, 64)

    gemm64<<<gg, 256>>>(q, Wq, bq, nullptr, 0);   // -> g_qh [B,H,S,d]
    gemm64<<<gg, 256>>>(k, Wk, bk, nullptr, 1);   // -> g_kh
    gemm64<<<gg, 256>>>(v, Wv, bv, nullptr, 2);   // -> g_vh

    attn_row<<<dim3(SEQ, BH), 128>>>(mask, attn_out, writeAttn);  // -> g_ctx (+ attn)

    gemm64<<<gg, 256>>>(nullptr, Wo, bo, out, 3); // ctx @ Wo + bo -> out
}

// round 2
// speedup vs baseline: 2.8947x; 2.8947x over previous
#include <cuda_runtime.h>
#include <math_constants.h>

// Problem constants
#define D_MODEL   1024
#define NUM_HEADS 16
#define DEPTH     64
#define BATCH     2
#define SEQ       2048
#define BH        (BATCH*NUM_HEADS)     // 32
#define M_ROWS    (BATCH*SEQ)           // 4096

// -------- device scratch (allocation-free workaround) --------
__device__ float g_qh[BH*SEQ*DEPTH];     // [B,H,S,d]
__device__ float g_kh[BH*SEQ*DEPTH];
__device__ float g_vh[BH*SEQ*DEPTH];
__device__ float g_ctx[M_ROWS*D_MODEL];  // [B,S,D] pre-Wo context
__device__ float g_m[BH*SEQ];            // softmax row max (for attn output)
__device__ float g_l[BH*SEQ];            // softmax row sum

// ============================================================
// 128x128x16 fp32 GEMM: Y = X[M,1024] @ W[1024,1024] + bias
// 256 threads, 8x8 microtile per thread.
// mode 0/1/2: Y = g_qh/g_kh/g_vh head-split [B,H,S,d]; mode 3: Y=Yext
// ============================================================
__global__ void gemm128(const float* __restrict__ Xext,
                        const float* __restrict__ W,
                        const float* __restrict__ bias,
                        float* __restrict__ Yext,
                        int mode)
{
    const int K = D_MODEL, N = D_MODEL;
    const float* X = (mode == 3) ? g_ctx : Xext;
    float* Y;
    if      (mode == 0) Y = g_qh;
    else if (mode == 1) Y = g_kh;
    else if (mode == 2) Y = g_vh;
    else                Y = Yext;

    __shared__ float As[16 * 132];   // A^T tile: [k][row], padded stride
    __shared__ float Bs[16 * 128];   // [k][col]

    const int tid  = threadIdx.x;
    const int tx   = tid & 15;
    const int ty   = tid >> 4;
    const int row0 = blockIdx.y * 128;
    const int col0 = blockIdx.x * 128;

    // load assignments
    const int ar = tid >> 1;          // 0..127
    const int ak = (tid & 1) * 8;     // 0 or 8
    const int bk = tid >> 4;          // 0..15
    const int bc = (tid & 15) * 8;    // 0..120

    float acc[8][8];
#pragma unroll
    for (int i = 0; i < 8; i++)
#pragma unroll
        for (int j = 0; j < 8; j++) acc[i][j] = 0.f;

    for (int k0 = 0; k0 < K; k0 += 16) {
        // A tile: 128 rows x 16 k
        float4 a0 = *(const float4*)(X + (size_t)(row0 + ar) * K + k0 + ak);
        float4 a1 = *(const float4*)(X + (size_t)(row0 + ar) * K + k0 + ak + 4);
        As[(ak + 0) * 132 + ar] = a0.x;
        As[(ak + 1) * 132 + ar] = a0.y;
        As[(ak + 2) * 132 + ar] = a0.z;
        As[(ak + 3) * 132 + ar] = a0.w;
        As[(ak + 4) * 132 + ar] = a1.x;
        As[(ak + 5) * 132 + ar] = a1.y;
        As[(ak + 6) * 132 + ar] = a1.z;
        As[(ak + 7) * 132 + ar] = a1.w;
        // B tile: 16 k x 128 cols
        float4 b0 = *(const float4*)(W + (size_t)(k0 + bk) * N + col0 + bc);
        float4 b1 = *(const float4*)(W + (size_t)(k0 + bk) * N + col0 + bc + 4);
        *(float4*)(Bs + bk * 128 + bc)     = b0;
        *(float4*)(Bs + bk * 128 + bc + 4) = b1;
        __syncthreads();

#pragma unroll
        for (int k = 0; k < 16; k++) {
            float a[8], b[8];
            *(float4*)(a)     = *(const float4*)(As + k * 132 + ty * 8);
            *(float4*)(a + 4) = *(const float4*)(As + k * 132 + ty * 8 + 4);
            *(float4*)(b)     = *(const float4*)(Bs + k * 128 + tx * 8);
            *(float4*)(b + 4) = *(const float4*)(Bs + k * 128 + tx * 8 + 4);
#pragma unroll
            for (int i = 0; i < 8; i++)
#pragma unroll
                for (int j = 0; j < 8; j++)
                    acc[i][j] += a[i] * b[j];
        }
        __syncthreads();
    }

    // epilogue
#pragma unroll
    for (int i = 0; i < 8; i++) {
        int r = row0 + ty * 8 + i;
#pragma unroll
        for (int j = 0; j < 8; j++) {
            int c = col0 + tx * 8 + j;
            float v = acc[i][j] + bias[c];
            if (mode <= 2) {
                int b_ = r >> 11;           // SEQ = 2048
                int s_ = r & (SEQ - 1);
                int h  = c >> 6;            // DEPTH = 64
                int dd = c & 63;
                Y[(size_t)(((b_ << 4) + h) * SEQ + s_) * DEPTH + dd] = v;
            } else {
                Y[(size_t)r * D_MODEL + c] = v;
            }
        }
    }
}

// ---- warp-group (16-lane) reductions; tid = ty*16+tx so lanes with the
// ---- same ty are 16 consecutive lanes within a half-warp.
__device__ __forceinline__ float red16_max(float v) {
#pragma unroll
    for (int off = 1; off < 16; off <<= 1)
        v = fmaxf(v, __shfl_xor_sync(0xffffffffu, v, off));
    return v;
}
__device__ __forceinline__ float red16_sum(float v) {
#pragma unroll
    for (int off = 1; off < 16; off <<= 1)
        v += __shfl_xor_sync(0xffffffffu, v, off);
    return v;
}

// ============================================================
// Flash attention fp32: block = 256 threads handles (bh, 64-query tile).
// Iterates causal key tiles of 64; K/V staged in smem, reused by 64 queries.
// Writes context into g_ctx and row stats into g_m/g_l.
// Dynamic smem: Qs[64*65] Ks[64*65] Ps[64*65] Vs[64*68] + mask[4096B]
// ============================================================
#define QS_STR 65
#define VS_STR 68
#define SM_Q   0
#define SM_K   (64*QS_STR)
#define SM_P   (2*64*QS_STR)
#define SM_V   (3*64*QS_STR)
#define SM_FLOATS (3*64*QS_STR + 64*VS_STR)
#define FLASH_SMEM (SM_FLOATS*4 + 64*64)

__global__ void attn_flash(const unsigned char* __restrict__ mask)
{
    extern __shared__ float sm[];
    float* Qs = sm + SM_Q;
    float* Ks = sm + SM_K;
    float* Ps = sm + SM_P;
    float* Vs = sm + SM_V;
    unsigned char* Ms = (unsigned char*)(sm + SM_FLOATS);

    const int bh = blockIdx.y;
    const int b_ = bh >> 4;
    const int h  = bh & 15;
    const int qt = gridDim.x - 1 - blockIdx.x;   // heavy tiles launch first
    const int i0 = qt * 64;

    const int tid = threadIdx.x;
    const int tx  = tid & 15;
    const int ty  = tid >> 4;
    const int r0  = ty * 4;       // local query rows r0..r0+3
    const int c0  = tx * 4;       // local key cols / d cols

    const float* qb = g_qh + (size_t)bh * SEQ * DEPTH;
    const float* kb = g_kh + (size_t)bh * SEQ * DEPTH;
    const float* vb = g_vh + (size_t)bh * SEQ * DEPTH;
    const unsigned char* mb = mask + (size_t)b_ * SEQ * SEQ;

    // load Q tile [64][64] natural layout, stride 65
    for (int idx = tid; idx < 1024; idx += 256) {
        int r  = idx >> 4;
        int d4 = (idx & 15) << 2;
        float4 qv = *(const float4*)(qb + (size_t)(i0 + r) * DEPTH + d4);
        float* dst = Qs + r * QS_STR + d4;
        dst[0] = qv.x; dst[1] = qv.y; dst[2] = qv.z; dst[3] = qv.w;
    }

    float o[4][4];
#pragma unroll
    for (int i = 0; i < 4; i++)
#pragma unroll
        for (int j = 0; j < 4; j++) o[i][j] = 0.f;
    float m_r[4], l_r[4];
#pragma unroll
    for (int i = 0; i < 4; i++) { m_r[i] = -CUDART_INF_F; l_r[i] = 0.f; }

    const int ntiles = qt + 1;
    for (int t = 0; t < ntiles; t++) {
        const int j0 = t * 64;
        // load K tile (natural [c][d], stride 65), V tile (stride 68), mask tile
        for (int idx = tid; idx < 1024; idx += 256) {
            int r  = idx >> 4;
            int d4 = (idx & 15) << 2;
            float4 kv = *(const float4*)(kb + (size_t)(j0 + r) * DEPTH + d4);
            float* dst = Ks + r * QS_STR + d4;
            dst[0] = kv.x; dst[1] = kv.y; dst[2] = kv.z; dst[3] = kv.w;
            float4 vv = *(const float4*)(vb + (size_t)(j0 + r) * DEPTH + d4);
            *(float4*)(Vs + r * VS_STR + d4) = vv;
        }
        {   // mask tile: 4096 bytes = 256 uint4
            int r   = tid >> 2;
            int c16 = (tid & 3) << 4;
            *(uint4*)(Ms + r * 64 + c16) =
                *(const uint4*)(mb + (size_t)(i0 + r) * SEQ + j0 + c16);
        }
        __syncthreads();

        // S = Q K^T (64x64x64), k-dim = d
        float s[4][4];
#pragma unroll
        for (int i = 0; i < 4; i++)
#pragma unroll
            for (int j = 0; j < 4; j++) s[i][j] = 0.f;
#pragma unroll 16
        for (int k = 0; k < 64; k++) {
            float a[4], b[4];
#pragma unroll
            for (int i = 0; i < 4; i++) a[i] = Qs[(r0 + i) * QS_STR + k];
#pragma unroll
            for (int j = 0; j < 4; j++) b[j] = Ks[(c0 + j) * QS_STR + k];
#pragma unroll
            for (int i = 0; i < 4; i++)
#pragma unroll
                for (int j = 0; j < 4; j++)
                    s[i][j] += a[i] * b[j];
        }

        // scale + RPE + masks
#pragma unroll
        for (int i = 0; i < 4; i++) {
            int ig = i0 + r0 + i;
#pragma unroll
            for (int j = 0; j < 4; j++) {
                int jg = j0 + c0 + j;
                float sv = s[i][j] * 0.125f + (float)(jg - ig);
                bool bad = (jg > ig) || Ms[(r0 + i) * 64 + (c0 + j)];
                s[i][j] = bad ? -1e9f : sv;
            }
        }

        // online softmax update
#pragma unroll
        for (int i = 0; i < 4; i++) {
            float rm = fmaxf(fmaxf(s[i][0], s[i][1]), fmaxf(s[i][2], s[i][3]));
            rm = red16_max(rm);
            float mn = fmaxf(m_r[i], rm);
            float al = __expf(m_r[i] - mn);
            float rs = 0.f;
#pragma unroll
            for (int j = 0; j < 4; j++) {
                float p = __expf(s[i][j] - mn);
                rs += p;
                Ps[(r0 + i) * QS_STR + c0 + j] = p;
            }
            rs = red16_sum(rs);
            l_r[i] = l_r[i] * al + rs;
            m_r[i] = mn;
#pragma unroll
            for (int j = 0; j < 4; j++) o[i][j] *= al;
        }
        __syncthreads();

        // O += P V (64x64x64), k-dim = key
#pragma unroll 16
        for (int k = 0; k < 64; k++) {
            float a[4], b[4];
#pragma unroll
            for (int i = 0; i < 4; i++) a[i] = Ps[(r0 + i) * QS_STR + k];
#pragma unroll
            for (int j = 0; j < 4; j++) b[j] = Vs[k * VS_STR + c0 + j];
#pragma unroll
            for (int i = 0; i < 4; i++)
#pragma unroll
                for (int j = 0; j < 4; j++)
                    o[i][j] += a[i] * b[j];
        }
        __syncthreads();
    }

    // epilogue: normalize, write context + stats
#pragma unroll
    for (int i = 0; i < 4; i++) {
        int ig = i0 + r0 + i;
        float inv = 1.0f / l_r[i];
        float4 ov;
        ov.x = o[i][0] * inv; ov.y = o[i][1] * inv;
        ov.z = o[i][2] * inv; ov.w = o[i][3] * inv;
        *(float4*)(g_ctx + (size_t)(b_ * SEQ + ig) * D_MODEL + h * DEPTH + c0) = ov;
        if (tx == 0) {
            g_m[(size_t)bh * SEQ + ig] = m_r[i];
            g_l[(size_t)bh * SEQ + ig] = l_r[i];
        }
    }
}

// ============================================================
// Optional: write full attention probabilities [BH,S,S] using saved stats.
// Recomputes QK^T per tile; zeros strictly-upper tiles.
// ============================================================
__global__ void attn_probs(const unsigned char* __restrict__ mask,
                           float* __restrict__ attn)
{
    __shared__ float Qs[64 * QS_STR];
    __shared__ float Ks[64 * QS_STR];
    __shared__ unsigned char Ms[64 * 64];

    const int bh = blockIdx.y;
    const int b_ = bh >> 4;
    const int qt = blockIdx.x;
    const int i0 = qt * 64;

    const int tid = threadIdx.x;
    const int tx  = tid & 15;
    const int ty  = tid >> 4;
    const int r0  = ty * 4;
    const int c0  = tx * 4;

    const float* qb = g_qh + (size_t)bh * SEQ * DEPTH;
    const float* kb = g_kh + (size_t)bh * SEQ * DEPTH;
    const unsigned char* mb = mask + (size_t)b_ * SEQ * SEQ;

    for (int idx = tid; idx < 1024; idx += 256) {
        int r  = idx >> 4;
        int d4 = (idx & 15) << 2;
        float4 qv = *(const float4*)(qb + (size_t)(i0 + r) * DEPTH + d4);
        float* dst = Qs + r * QS_STR + d4;
        dst[0] = qv.x; dst[1] = qv.y; dst[2] = qv.z; dst[3] = qv.w;
    }

    float mi[4], li[4];
#pragma unroll
    for (int i = 0; i < 4; i++) {
        mi[i] = g_m[(size_t)bh * SEQ + i0 + r0 + i];
        li[i] = 1.0f / g_l[(size_t)bh * SEQ + i0 + r0 + i];
    }
    __syncthreads();

    for (int jt = 0; jt < SEQ / 64; jt++) {
        const int j0 = jt * 64;
        if (j0 > i0 + 63) {
            // strictly-upper tile -> zeros
            for (int idx = tid; idx < 1024; idx += 256) {
                int r  = idx >> 4;
                int c4 = (idx & 15) << 2;
                float4 z = {0.f, 0.f, 0.f, 0.f};
                *(float4*)(attn + ((size_t)bh * SEQ + i0 + r) * SEQ + j0 + c4) = z;
            }
            continue;
        }
        for (int idx = tid; idx < 1024; idx += 256) {
            int r  = idx >> 4;
            int d4 = (idx & 15) << 2;
            float4 kv = *(const float4*)(kb + (size_t)(j0 + r) * DEPTH + d4);
            float* dst = Ks + r * QS_STR + d4;
            dst[0] = kv.x; dst[1] = kv.y; dst[2] = kv.z; dst[3] = kv.w;
        }
        {
            int r   = tid >> 2;
            int c16 = (tid & 3) << 4;
            *(uint4*)(Ms + r * 64 + c16) =
                *(const uint4*)(mb + (size_t)(i0 + r) * SEQ + j0 + c16);
        }
        __syncthreads();

        float s[4][4];
#pragma unroll
        for (int i = 0; i < 4; i++)
#pragma unroll
            for (int j = 0; j < 4; j++) s[i][j] = 0.f;
#pragma unroll 16
        for (int k = 0; k < 64; k++) {
            float a[4], b[4];
#pragma unroll
            for (int i = 0; i < 4; i++) a[i] = Qs[(r0 + i) * QS_STR + k];
#pragma unroll
            for (int j = 0; j < 4; j++) b[j] = Ks[(c0 + j) * QS_STR + k];
#pragma unroll
            for (int i = 0; i < 4; i++)
#pragma unroll
                for (int j = 0; j < 4; j++)
                    s[i][j] += a[i] * b[j];
        }

#pragma unroll
        for (int i = 0; i < 4; i++) {
            int ig = i0 + r0 + i;
            float4 ov;
            float* pv = (float*)&ov;
#pragma unroll
            for (int j = 0; j < 4; j++) {
                int jg = j0 + c0 + j;
                float sv = s[i][j] * 0.125f + (float)(jg - ig);
                bool bad = (jg > ig) || Ms[(r0 + i) * 64 + (c0 + j)];
                pv[j] = bad ? 0.f : __expf(sv - mi[i]) * li[i];
            }
            *(float4*)(attn + ((size_t)bh * SEQ + ig) * SEQ + j0 + c0) = ov;
        }
        __syncthreads();
    }
}

// ============================================================
extern "C" void kernel_launch(void* const* d_in, const int* in_sizes, int n_in,
                              void* d_out, int out_size)
{
    const float* q  = (const float*)d_in[0];
    const float* k  = (const float*)d_in[1];
    const float* v  = (const float*)d_in[2];
    const float* Wq = (const float*)d_in[3];
    const float* bq = (const float*)d_in[4];
    const float* Wk = (const float*)d_in[5];
    const float* bk = (const float*)d_in[6];
    const float* Wv = (const float*)d_in[7];
    const float* bv = (const float*)d_in[8];
    const float* Wo = (const float*)d_in[9];
    const float* bo = (const float*)d_in[10];
    const unsigned char* mask = (const unsigned char*)d_in[11];

    float* out = (float*)d_out;
    const long long OUT_ELEMS = (long long)BATCH * SEQ * D_MODEL;  // 4,194,304
    const int writeAttn = ((long long)out_size > OUT_ELEMS) ? 1 : 0;
    float* attn_out = out + OUT_ELEMS;   // tuple order: (out, attn)

    cudaFuncSetAttribute(attn_flash,
                         cudaFuncAttributeMaxDynamicSharedMemorySize, FLASH_SMEM);

    dim3 gg(D_MODEL / 128, M_ROWS / 128);  // (8, 32)
    gemm128<<<gg, 256>>>(q, Wq, bq, nullptr, 0);   // -> g_qh
    gemm128<<<gg, 256>>>(k, Wk, bk, nullptr, 1);   // -> g_kh
    gemm128<<<gg, 256>>>(v, Wv, bv, nullptr, 2);   // -> g_vh

    attn_flash<<<dim3(SEQ / 64, BH), 256, FLASH_SMEM>>>(mask);   // -> g_ctx

    if (writeAttn)
        attn_probs<<<dim3(SEQ / 64, BH), 256>>>(mask, attn_out);

    gemm128<<<gg, 256>>>(nullptr, Wo, bo, out, 3); // ctx @ Wo + bo -> out
}

// round 3
// speedup vs baseline: 3.7462x; 1.2942x over previous
#include <cuda_runtime.h>
#include <cuda_bf16.h>
#include <math_constants.h>
#include <cstdint>

// Problem constants
#define D_MODEL   1024
#define NUM_HEADS 16
#define DEPTH     64
#define BATCH     2
#define SEQ       2048
#define BH        (BATCH*NUM_HEADS)     // 32
#define M_ROWS    (BATCH*SEQ)           // 4096

// -------- device scratch (allocation-free workaround) --------
__device__ float g_qh[BH*SEQ*DEPTH];     // [B,H,S,d]
__device__ float g_kh[BH*SEQ*DEPTH];
__device__ float g_vh[BH*SEQ*DEPTH];
__device__ float g_ctx[M_ROWS*D_MODEL];  // [B,S,D] pre-Wo context
__device__ float g_m[BH*SEQ];            // softmax row max
__device__ float g_l[BH*SEQ];            // softmax row sum
// bf16 split buffers (activation X and transposed weight W^T)
__device__ __nv_bfloat16 g_ah[M_ROWS*D_MODEL];
__device__ __nv_bfloat16 g_al[M_ROWS*D_MODEL];
__device__ __nv_bfloat16 g_wth[D_MODEL*D_MODEL];   // W^T[n][k] hi
__device__ __nv_bfloat16 g_wtl[D_MODEL*D_MODEL];   // W^T[n][k] lo

// ============================================================
// Conversion kernels: fp32 -> bf16 hi/lo split
// ============================================================
__global__ void cvt_x(const float* __restrict__ Xext, int n, int useCtx)
{
    const float* src = useCtx ? g_ctx : Xext;
    for (int i = blockIdx.x * blockDim.x + threadIdx.x; i < n;
         i += gridDim.x * blockDim.x) {
        float x = src[i];
        __nv_bfloat16 h = __float2bfloat16(x);
        g_ah[i] = h;
        g_al[i] = __float2bfloat16(x - __bfloat162float(h));
    }
}

__global__ void cvt_wT(const float* __restrict__ W)
{
    int i = blockIdx.x * 256 + threadIdx.x;   // 0 .. 1M-1
    int k = i >> 10;
    int n = i & 1023;
    float x = W[i];                            // W[k][n], coalesced read
    __nv_bfloat16 h = __float2bfloat16(x);
    g_wth[n * 1024 + k] = h;
    g_wtl[n * 1024 + k] = __float2bfloat16(x - __bfloat162float(h));
}

// ============================================================
// bf16-split tensor-core GEMM: Y = X[M,1024] @ W[1024,1024] + bias
//   C = Xhi@Whi + Xhi@Wlo + Xlo@Whi  (fp32 accumulate)
// Block 128x128, 8 warps (2x4), warp tile 64x32, BK=32, cp.async 2-stage.
// mode 0/1/2: Y = g_qh/g_kh/g_vh head-split; mode 3: Y = Yext linear.
// ============================================================
#define LDT      40                  // bf16 row stride (32 data + 8 pad)
#define LDW      (LDT/2)             // 20 uint32 words per row
#define TILE_BF  (128*LDT)           // 5120 bf16 per array
#define STAGE_BF (4*TILE_BF)         // Ah | Al | Bh | Bl
#define GEMM_SMEM (2*STAGE_BF*2)     // 2 stages * bytes

static __device__ __forceinline__ uint32_t s2u(const void* p) {
    return static_cast<uint32_t>(__cvta_generic_to_shared(p));
}
static __device__ __forceinline__ void cpa16(uint32_t s, const void* g) {
    asm volatile("cp.async.cg.shared.global [%0], [%1], 16;\n" :: "r"(s), "l"(g));
}

#define MMA16816(d, a, b) asm volatile( \
    "mma.sync.aligned.m16n8k16.row.col.f32.bf16.bf16.f32 " \
    "{%0,%1,%2,%3}, {%4,%5,%6,%7}, {%8,%9}, {%0,%1,%2,%3};" \
    : "+f"(d[0]), "+f"(d[1]), "+f"(d[2]), "+f"(d[3]) \
    : "r"(a[0]), "r"(a[1]), "r"(a[2]), "r"(a[3]), "r"(b[0]), "r"(b[1]))

__device__ __forceinline__ void load_stage(__nv_bfloat16* S,
    const __nv_bfloat16* gAh, const __nv_bfloat16* gAl,
    const __nv_bfloat16* gBh, const __nv_bfloat16* gBl,
    int k0, int tid)
{
#pragma unroll
    for (int r = 0; r < 2; r++) {
        int c   = tid + 256 * r;      // 0..511
        int row = c >> 2;             // 0..127
        int seg = c & 3;              // 0..3 (8 bf16 each)
        int go  = row * D_MODEL + k0 + seg * 8;
        int so  = row * LDT + seg * 8;
        cpa16(s2u(S + so),               gAh + go);
        cpa16(s2u(S + TILE_BF + so),     gAl + go);
        cpa16(s2u(S + 2 * TILE_BF + so), gBh + go);
        cpa16(s2u(S + 3 * TILE_BF + so), gBl + go);
    }
    asm volatile("cp.async.commit_group;\n" ::: "memory");
}

__global__ __launch_bounds__(256) void gemm_mma(const float* __restrict__ bias,
                                                float* __restrict__ Yext,
                                                int mode)
{
    extern __shared__ __nv_bfloat16 sm[];

    const int tid  = threadIdx.x;
    const int lane = tid & 31;
    const int warp = tid >> 5;
    const int wm   = warp >> 2;      // 0..1
    const int wn   = warp & 3;       // 0..3
    const int g    = lane >> 2;      // 0..7
    const int tig  = lane & 3;       // 0..3
    const int row0 = blockIdx.y * 128;
    const int col0 = blockIdx.x * 128;

    const __nv_bfloat16* gAh = g_ah  + (size_t)row0 * D_MODEL;
    const __nv_bfloat16* gAl = g_al  + (size_t)row0 * D_MODEL;
    const __nv_bfloat16* gBh = g_wth + (size_t)col0 * D_MODEL;
    const __nv_bfloat16* gBl = g_wtl + (size_t)col0 * D_MODEL;

    float acc[4][4][4];
#pragma unroll
    for (int mi = 0; mi < 4; mi++)
#pragma unroll
        for (int ni = 0; ni < 4; ni++)
#pragma unroll
            for (int r = 0; r < 4; r++) acc[mi][ni][r] = 0.f;

    load_stage(sm, gAh, gAl, gBh, gBl, 0, tid);

    const int NT = D_MODEL / 32;     // 32 k-tiles
    for (int t = 0; t < NT; t++) {
        if (t + 1 < NT)
            load_stage(sm + ((t + 1) & 1) * STAGE_BF, gAh, gAl, gBh, gBl,
                       (t + 1) * 32, tid);
        if (t + 1 < NT) asm volatile("cp.async.wait_group 1;\n" ::: "memory");
        else            asm volatile("cp.async.wait_group 0;\n" ::: "memory");
        __syncthreads();

        const __nv_bfloat16* S = sm + (t & 1) * STAGE_BF;
        const uint32_t* UAh = (const uint32_t*)(S);
        const uint32_t* UAl = (const uint32_t*)(S + TILE_BF);
        const uint32_t* UBh = (const uint32_t*)(S + 2 * TILE_BF);
        const uint32_t* UBl = (const uint32_t*)(S + 3 * TILE_BF);

#pragma unroll
        for (int ks = 0; ks < 2; ks++) {
            const int kw = ks * 8 + tig;
            uint32_t ah[4][4], al[4][4];
#pragma unroll
            for (int mi = 0; mi < 4; mi++) {
                int r = wm * 64 + mi * 16 + g;
                ah[mi][0] = UAh[r * LDW + kw];
                ah[mi][1] = UAh[(r + 8) * LDW + kw];
                ah[mi][2] = UAh[r * LDW + kw + 4];
                ah[mi][3] = UAh[(r + 8) * LDW + kw + 4];
                al[mi][0] = UAl[r * LDW + kw];
                al[mi][1] = UAl[(r + 8) * LDW + kw];
                al[mi][2] = UAl[r * LDW + kw + 4];
                al[mi][3] = UAl[(r + 8) * LDW + kw + 4];
            }
            uint32_t bh[4][2], bl[4][2];
#pragma unroll
            for (int ni = 0; ni < 4; ni++) {
                int cc = wn * 32 + ni * 8 + g;
                bh[ni][0] = UBh[cc * LDW + kw];
                bh[ni][1] = UBh[cc * LDW + kw + 4];
                bl[ni][0] = UBl[cc * LDW + kw];
                bl[ni][1] = UBl[cc * LDW + kw + 4];
            }
#pragma unroll
            for (int mi = 0; mi < 4; mi++)
#pragma unroll
                for (int ni = 0; ni < 4; ni++) {
                    MMA16816(acc[mi][ni], ah[mi], bh[ni]);
                    MMA16816(acc[mi][ni], ah[mi], bl[ni]);
                    MMA16816(acc[mi][ni], al[mi], bh[ni]);
                }
        }
        __syncthreads();
    }

    // epilogue
    float* Y;
    if      (mode == 0) Y = g_qh;
    else if (mode == 1) Y = g_kh;
    else if (mode == 2) Y = g_vh;
    else                Y = Yext;

#pragma unroll
    for (int mi = 0; mi < 4; mi++) {
#pragma unroll
        for (int ni = 0; ni < 4; ni++) {
            int r1 = row0 + wm * 64 + mi * 16 + g;
            int c  = col0 + wn * 32 + ni * 8 + 2 * tig;
            float v00 = acc[mi][ni][0] + bias[c];
            float v01 = acc[mi][ni][1] + bias[c + 1];
            float v10 = acc[mi][ni][2] + bias[c];
            float v11 = acc[mi][ni][3] + bias[c + 1];
            if (mode <= 2) {
                int h = c >> 6;
#pragma unroll
                for (int rr = 0; rr < 2; rr++) {
                    int r  = r1 + rr * 8;
                    int b_ = r >> 11;
                    int s_ = r & (SEQ - 1);
                    size_t base = (size_t)(((b_ << 4) + h) * SEQ + s_) * DEPTH + (c & 63);
                    Y[base]     = rr ? v10 : v00;
                    Y[base + 1] = rr ? v11 : v01;
                }
            } else {
                Y[(size_t)r1 * D_MODEL + c]           = v00;
                Y[(size_t)r1 * D_MODEL + c + 1]       = v01;
                Y[(size_t)(r1 + 8) * D_MODEL + c]     = v10;
                Y[(size_t)(r1 + 8) * D_MODEL + c + 1] = v11;
            }
        }
    }
}

// ---- 16-lane reductions
__device__ __forceinline__ float red16_max(float v) {
#pragma unroll
    for (int off = 1; off < 16; off <<= 1)
        v = fmaxf(v, __shfl_xor_sync(0xffffffffu, v, off));
    return v;
}
__device__ __forceinline__ float red16_sum(float v) {
#pragma unroll
    for (int off = 1; off < 16; off <<= 1)
        v += __shfl_xor_sync(0xffffffffu, v, off);
    return v;
}

// ============================================================
// Flash attention fp32 (unchanged from R2 — proven)
// ============================================================
#define QS_STR 65
#define VS_STR 68
#define SM_Q   0
#define SM_K   (64*QS_STR)
#define SM_P   (2*64*QS_STR)
#define SM_V   (3*64*QS_STR)
#define SM_FLOATS (3*64*QS_STR + 64*VS_STR)
#define FLASH_SMEM (SM_FLOATS*4 + 64*64)

__global__ void attn_flash(const unsigned char* __restrict__ mask)
{
    extern __shared__ float smf[];
    float* Qs = smf + SM_Q;
    float* Ks = smf + SM_K;
    float* Ps = smf + SM_P;
    float* Vs = smf + SM_V;
    unsigned char* Ms = (unsigned char*)(smf + SM_FLOATS);

    const int bh = blockIdx.y;
    const int b_ = bh >> 4;
    const int h  = bh & 15;
    const int qt = gridDim.x - 1 - blockIdx.x;
    const int i0 = qt * 64;

    const int tid = threadIdx.x;
    const int tx  = tid & 15;
    const int ty  = tid >> 4;
    const int r0  = ty * 4;
    const int c0  = tx * 4;

    const float* qb = g_qh + (size_t)bh * SEQ * DEPTH;
    const float* kb = g_kh + (size_t)bh * SEQ * DEPTH;
    const float* vb = g_vh + (size_t)bh * SEQ * DEPTH;
    const unsigned char* mb = mask + (size_t)b_ * SEQ * SEQ;

    for (int idx = tid; idx < 1024; idx += 256) {
        int r  = idx >> 4;
        int d4 = (idx & 15) << 2;
        float4 qv = *(const float4*)(qb + (size_t)(i0 + r) * DEPTH + d4);
        float* dst = Qs + r * QS_STR + d4;
        dst[0] = qv.x; dst[1] = qv.y; dst[2] = qv.z; dst[3] = qv.w;
    }

    float o[4][4];
#pragma unroll
    for (int i = 0; i < 4; i++)
#pragma unroll
        for (int j = 0; j < 4; j++) o[i][j] = 0.f;
    float m_r[4], l_r[4];
#pragma unroll
    for (int i = 0; i < 4; i++) { m_r[i] = -CUDART_INF_F; l_r[i] = 0.f; }

    const int ntiles = qt + 1;
    for (int t = 0; t < ntiles; t++) {
        const int j0 = t * 64;
        for (int idx = tid; idx < 1024; idx += 256) {
            int r  = idx >> 4;
            int d4 = (idx & 15) << 2;
            float4 kv = *(const float4*)(kb + (size_t)(j0 + r) * DEPTH + d4);
            float* dst = Ks + r * QS_STR + d4;
            dst[0] = kv.x; dst[1] = kv.y; dst[2] = kv.z; dst[3] = kv.w;
            float4 vv = *(const float4*)(vb + (size_t)(j0 + r) * DEPTH + d4);
            *(float4*)(Vs + r * VS_STR + d4) = vv;
        }
        {
            int r   = tid >> 2;
            int c16 = (tid & 3) << 4;
            *(uint4*)(Ms + r * 64 + c16) =
                *(const uint4*)(mb + (size_t)(i0 + r) * SEQ + j0 + c16);
        }
        __syncthreads();

        float s[4][4];
#pragma unroll
        for (int i = 0; i < 4; i++)
#pragma unroll
            for (int j = 0; j < 4; j++) s[i][j] = 0.f;
#pragma unroll 16
        for (int k = 0; k < 64; k++) {
            float a[4], b[4];
#pragma unroll
            for (int i = 0; i < 4; i++) a[i] = Qs[(r0 + i) * QS_STR + k];
#pragma unroll
            for (int j = 0; j < 4; j++) b[j] = Ks[(c0 + j) * QS_STR + k];
#pragma unroll
            for (int i = 0; i < 4; i++)
#pragma unroll
                for (int j = 0; j < 4; j++)
                    s[i][j] += a[i] * b[j];
        }

#pragma unroll
        for (int i = 0; i < 4; i++) {
            int ig = i0 + r0 + i;
#pragma unroll
            for (int j = 0; j < 4; j++) {
                int jg = j0 + c0 + j;
                float sv = s[i][j] * 0.125f + (float)(jg - ig);
                bool bad = (jg > ig) || Ms[(r0 + i) * 64 + (c0 + j)];
                s[i][j] = bad ? -1e9f : sv;
            }
        }

#pragma unroll
        for (int i = 0; i < 4; i++) {
            float rm = fmaxf(fmaxf(s[i][0], s[i][1]), fmaxf(s[i][2], s[i][3]));
            rm = red16_max(rm);
            float mn = fmaxf(m_r[i], rm);
            float al = __expf(m_r[i] - mn);
            float rs = 0.f;
#pragma unroll
            for (int j = 0; j < 4; j++) {
                float p = __expf(s[i][j] - mn);
                rs += p;
                Ps[(r0 + i) * QS_STR + c0 + j] = p;
            }
            rs = red16_sum(rs);
            l_r[i] = l_r[i] * al + rs;
            m_r[i] = mn;
#pragma unroll
            for (int j = 0; j < 4; j++) o[i][j] *= al;
        }
        __syncthreads();

#pragma unroll 16
        for (int k = 0; k < 64; k++) {
            float a[4], b[4];
#pragma unroll
            for (int i = 0; i < 4; i++) a[i] = Ps[(r0 + i) * QS_STR + k];
#pragma unroll
            for (int j = 0; j < 4; j++) b[j] = Vs[k * VS_STR + c0 + j];
#pragma unroll
            for (int i = 0; i < 4; i++)
#pragma unroll
                for (int j = 0; j < 4; j++)
                    o[i][j] += a[i] * b[j];
        }
        __syncthreads();
    }

#pragma unroll
    for (int i = 0; i < 4; i++) {
        int ig = i0 + r0 + i;
        float inv = 1.0f / l_r[i];
        float4 ov;
        ov.x = o[i][0] * inv; ov.y = o[i][1] * inv;
        ov.z = o[i][2] * inv; ov.w = o[i][3] * inv;
        *(float4*)(g_ctx + (size_t)(b_ * SEQ + ig) * D_MODEL + h * DEPTH + c0) = ov;
        if (tx == 0) {
            g_m[(size_t)bh * SEQ + ig] = m_r[i];
            g_l[(size_t)bh * SEQ + ig] = l_r[i];
        }
    }
}

// ============================================================
// Optional full attention probabilities (unchanged from R2)
// ============================================================
__global__ void attn_probs(const unsigned char* __restrict__ mask,
                           float* __restrict__ attn)
{
    __shared__ float Qs[64 * QS_STR];
    __shared__ float Ks[64 * QS_STR];
    __shared__ unsigned char Ms[64 * 64];

    const int bh = blockIdx.y;
    const int b_ = bh >> 4;
    const int qt = blockIdx.x;
    const int i0 = qt * 64;

    const int tid = threadIdx.x;
    const int tx  = tid & 15;
    const int ty  = tid >> 4;
    const int r0  = ty * 4;
    const int c0  = tx * 4;

    const float* qb = g_qh + (size_t)bh * SEQ * DEPTH;
    const float* kb = g_kh + (size_t)bh * SEQ * DEPTH;
    const unsigned char* mb = mask + (size_t)b_ * SEQ * SEQ;

    for (int idx = tid; idx < 1024; idx += 256) {
        int r  = idx >> 4;
        int d4 = (idx & 15) << 2;
        float4 qv = *(const float4*)(qb + (size_t)(i0 + r) * DEPTH + d4);
        float* dst = Qs + r * QS_STR + d4;
        dst[0] = qv.x; dst[1] = qv.y; dst[2] = qv.z; dst[3] = qv.w;
    }

    float mi[4], li[4];
#pragma unroll
    for (int i = 0; i < 4; i++) {
        mi[i] = g_m[(size_t)bh * SEQ + i0 + r0 + i];
        li[i] = 1.0f / g_l[(size_t)bh * SEQ + i0 + r0 + i];
    }
    __syncthreads();

    for (int jt = 0; jt < SEQ / 64; jt++) {
        const int j0 = jt * 64;
        if (j0 > i0 + 63) {
            for (int idx = tid; idx < 1024; idx += 256) {
                int r  = idx >> 4;
                int c4 = (idx & 15) << 2;
                float4 z = {0.f, 0.f, 0.f, 0.f};
                *(float4*)(attn + ((size_t)bh * SEQ + i0 + r) * SEQ + j0 + c4) = z;
            }
            continue;
        }
        for (int idx = tid; idx < 1024; idx += 256) {
            int r  = idx >> 4;
            int d4 = (idx & 15) << 2;
            float4 kv = *(const float4*)(kb + (size_t)(j0 + r) * DEPTH + d4);
            float* dst = Ks + r * QS_STR + d4;
            dst[0] = kv.x; dst[1] = kv.y; dst[2] = kv.z; dst[3] = kv.w;
        }
        {
            int r   = tid >> 2;
            int c16 = (tid & 3) << 4;
            *(uint4*)(Ms + r * 64 + c16) =
                *(const uint4*)(mb + (size_t)(i0 + r) * SEQ + j0 + c16);
        }
        __syncthreads();

        float s[4][4];
#pragma unroll
        for (int i = 0; i < 4; i++)
#pragma unroll
            for (int j = 0; j < 4; j++) s[i][j] = 0.f;
#pragma unroll 16
        for (int k = 0; k < 64; k++) {
            float a[4], b[4];
#pragma unroll
            for (int i = 0; i < 4; i++) a[i] = Qs[(r0 + i) * QS_STR + k];
#pragma unroll
            for (int j = 0; j < 4; j++) b[j] = Ks[(c0 + j) * QS_STR + k];
#pragma unroll
            for (int i = 0; i < 4; i++)
#pragma unroll
                for (int j = 0; j < 4; j++)
                    s[i][j] += a[i] * b[j];
        }

#pragma unroll
        for (int i = 0; i < 4; i++) {
            int ig = i0 + r0 + i;
            float4 ov;
            float* pv = (float*)&ov;
#pragma unroll
            for (int j = 0; j < 4; j++) {
                int jg = j0 + c0 + j;
                float sv = s[i][j] * 0.125f + (float)(jg - ig);
                bool bad = (jg > ig) || Ms[(r0 + i) * 64 + (c0 + j)];
                pv[j] = bad ? 0.f : __expf(sv - mi[i]) * li[i];
            }
            *(float4*)(attn + ((size_t)bh * SEQ + ig) * SEQ + j0 + c0) = ov;
        }
        __syncthreads();
    }
}

// ============================================================
extern "C" void kernel_launch(void* const* d_in, const int* in_sizes, int n_in,
                              void* d_out, int out_size)
{
    const float* q  = (const float*)d_in[0];
    const float* k  = (const float*)d_in[1];
    const float* v  = (const float*)d_in[2];
    const float* Wq = (const float*)d_in[3];
    const float* bq = (const float*)d_in[4];
    const float* Wk = (const float*)d_in[5];
    const float* bk = (const float*)d_in[6];
    const float* Wv = (const float*)d_in[7];
    const float* bv = (const float*)d_in[8];
    const float* Wo = (const float*)d_in[9];
    const float* bo = (const float*)d_in[10];
    const unsigned char* mask = (const unsigned char*)d_in[11];

    float* out = (float*)d_out;
    const long long OUT_ELEMS = (long long)BATCH * SEQ * D_MODEL;
    const int writeAttn = ((long long)out_size > OUT_ELEMS) ? 1 : 0;
    float* attn_out = out + OUT_ELEMS;

    static int attrs_set = 0;
    cudaFuncSetAttribute(attn_flash,
                         cudaFuncAttributeMaxDynamicSharedMemorySize, FLASH_SMEM);
    cudaFuncSetAttribute(gemm_mma,
                         cudaFuncAttributeMaxDynamicSharedMemorySize, GEMM_SMEM);
    (void)attrs_set;

    const int NX = M_ROWS * D_MODEL;
    dim3 gg(D_MODEL / 128, M_ROWS / 128);   // (8, 32)

    // Q projection
    cvt_wT<<<4096, 256>>>(Wq);
    cvt_x<<<2048, 256>>>(q, NX, 0);
    gemm_mma<<<gg, 256, GEMM_SMEM>>>(bq, nullptr, 0);
    // K projection
    cvt_wT<<<4096, 256>>>(Wk);
    cvt_x<<<2048, 256>>>(k, NX, 0);
    gemm_mma<<<gg, 256, GEMM_SMEM>>>(bk, nullptr, 1);
    // V projection
    cvt_wT<<<4096, 256>>>(Wv);
    cvt_x<<<2048, 256>>>(v, NX, 0);
    gemm_mma<<<gg, 256, GEMM_SMEM>>>(bv, nullptr, 2);

    // attention
    attn_flash<<<dim3(SEQ / 64, BH), 256, FLASH_SMEM>>>(mask);
    if (writeAttn)
        attn_probs<<<dim3(SEQ / 64, BH), 256>>>(mask, attn_out);

    // output projection
    cvt_wT<<<4096, 256>>>(Wo);
    cvt_x<<<2048, 256>>>(nullptr, NX, 1);
    gemm_mma<<<gg, 256, GEMM_SMEM>>>(bo, out, 3);
}

// round 4
// speedup vs baseline: 4.9760x; 1.3283x over previous
#include <cuda_runtime.h>
#include <cuda_bf16.h>
#include <math_constants.h>
#include <cstdint>

// Problem constants
#define D_MODEL   1024
#define NUM_HEADS 16
#define DEPTH     64
#define BATCH     2
#define SEQ       2048
#define BH        (BATCH*NUM_HEADS)     // 32
#define M_ROWS    (BATCH*SEQ)           // 4096

// -------- device scratch (allocation-free workaround) --------
__device__ float g_m[BH*SEQ];            // softmax row max
__device__ float g_l[BH*SEQ];            // softmax row sum
// bf16 split buffers
__device__ __align__(16) __nv_bfloat16 g_ah[M_ROWS*D_MODEL];   // GEMM A hi (inputs / ctx)
__device__ __align__(16) __nv_bfloat16 g_al[M_ROWS*D_MODEL];   // GEMM A lo
__device__ __align__(16) __nv_bfloat16 g_wth[D_MODEL*D_MODEL]; // W^T hi
__device__ __align__(16) __nv_bfloat16 g_wtl[D_MODEL*D_MODEL]; // W^T lo
__device__ __align__(16) __nv_bfloat16 g_qhh[BH*SEQ*DEPTH];    // Q head-split hi
__device__ __align__(16) __nv_bfloat16 g_qhl[BH*SEQ*DEPTH];
__device__ __align__(16) __nv_bfloat16 g_khh[BH*SEQ*DEPTH];    // K head-split hi
__device__ __align__(16) __nv_bfloat16 g_khl[BH*SEQ*DEPTH];
__device__ __align__(16) __nv_bfloat16 g_vth[BH*DEPTH*SEQ];    // V^T [bh][d][s] hi
__device__ __align__(16) __nv_bfloat16 g_vtl[BH*DEPTH*SEQ];

// ============================================================
// Conversion kernels: fp32 -> bf16 hi/lo split
// ============================================================
__global__ void cvt_x(const float* __restrict__ src, int n)
{
    for (int i = blockIdx.x * blockDim.x + threadIdx.x; i < n;
         i += gridDim.x * blockDim.x) {
        float x = src[i];
        __nv_bfloat16 h = __float2bfloat16(x);
        g_ah[i] = h;
        g_al[i] = __float2bfloat16(x - __bfloat162float(h));
    }
}

__global__ void cvt_wT(const float* __restrict__ W)
{
    int i = blockIdx.x * 256 + threadIdx.x;   // 0 .. 1M-1
    int k = i >> 10;
    int n = i & 1023;
    float x = W[i];                            // W[k][n], coalesced read
    __nv_bfloat16 h = __float2bfloat16(x);
    g_wth[n * 1024 + k] = h;
    g_wtl[n * 1024 + k] = __float2bfloat16(x - __bfloat162float(h));
}

// ============================================================
// bf16-split tensor-core GEMM (as R3), epilogue writes bf16 splits
// mode 0: Q -> g_qhh/g_qhl ; mode 1: K -> g_khh/g_khl
// mode 2: V -> g_vth/g_vtl (transposed) ; mode 3: fp32 -> Yext
// ============================================================
#define LDT      40
#define LDW      (LDT/2)
#define TILE_BF  (128*LDT)
#define STAGE_BF (4*TILE_BF)
#define GEMM_SMEM (2*STAGE_BF*2)

static __device__ __forceinline__ uint32_t s2u(const void* p) {
    return static_cast<uint32_t>(__cvta_generic_to_shared(p));
}
static __device__ __forceinline__ void cpa16(uint32_t s, const void* g) {
    asm volatile("cp.async.cg.shared.global [%0], [%1], 16;\n" :: "r"(s), "l"(g));
}

#define MMA16816(d, a, b) asm volatile( \
    "mma.sync.aligned.m16n8k16.row.col.f32.bf16.bf16.f32 " \
    "{%0,%1,%2,%3}, {%4,%5,%6,%7}, {%8,%9}, {%0,%1,%2,%3};" \
    : "+f"(d[0]), "+f"(d[1]), "+f"(d[2]), "+f"(d[3]) \
    : "r"(a[0]), "r"(a[1]), "r"(a[2]), "r"(a[3]), "r"(b[0]), "r"(b[1]))

__device__ __forceinline__ void load_stage(__nv_bfloat16* S,
    const __nv_bfloat16* gAh, const __nv_bfloat16* gAl,
    const __nv_bfloat16* gBh, const __nv_bfloat16* gBl,
    int k0, int tid)
{
#pragma unroll
    for (int r = 0; r < 2; r++) {
        int c   = tid + 256 * r;
        int row = c >> 2;
        int seg = c & 3;
        int go  = row * D_MODEL + k0 + seg * 8;
        int so  = row * LDT + seg * 8;
        cpa16(s2u(S + so),               gAh + go);
        cpa16(s2u(S + TILE_BF + so),     gAl + go);
        cpa16(s2u(S + 2 * TILE_BF + so), gBh + go);
        cpa16(s2u(S + 3 * TILE_BF + so), gBl + go);
    }
    asm volatile("cp.async.commit_group;\n" ::: "memory");
}

__global__ __launch_bounds__(256) void gemm_mma(const float* __restrict__ bias,
                                                float* __restrict__ Yext,
                                                int mode)
{
    extern __shared__ __nv_bfloat16 sm[];

    const int tid  = threadIdx.x;
    const int lane = tid & 31;
    const int warp = tid >> 5;
    const int wm   = warp >> 2;
    const int wn   = warp & 3;
    const int g    = lane >> 2;
    const int tig  = lane & 3;
    const int row0 = blockIdx.y * 128;
    const int col0 = blockIdx.x * 128;

    const __nv_bfloat16* gAh = g_ah  + (size_t)row0 * D_MODEL;
    const __nv_bfloat16* gAl = g_al  + (size_t)row0 * D_MODEL;
    const __nv_bfloat16* gBh = g_wth + (size_t)col0 * D_MODEL;
    const __nv_bfloat16* gBl = g_wtl + (size_t)col0 * D_MODEL;

    float acc[4][4][4];
#pragma unroll
    for (int mi = 0; mi < 4; mi++)
#pragma unroll
        for (int ni = 0; ni < 4; ni++)
#pragma unroll
            for (int r = 0; r < 4; r++) acc[mi][ni][r] = 0.f;

    load_stage(sm, gAh, gAl, gBh, gBl, 0, tid);

    const int NT = D_MODEL / 32;
    for (int t = 0; t < NT; t++) {
        if (t + 1 < NT)
            load_stage(sm + ((t + 1) & 1) * STAGE_BF, gAh, gAl, gBh, gBl,
                       (t + 1) * 32, tid);
        if (t + 1 < NT) asm volatile("cp.async.wait_group 1;\n" ::: "memory");
        else            asm volatile("cp.async.wait_group 0;\n" ::: "memory");
        __syncthreads();

        const __nv_bfloat16* S = sm + (t & 1) * STAGE_BF;
        const uint32_t* UAh = (const uint32_t*)(S);
        const uint32_t* UAl = (const uint32_t*)(S + TILE_BF);
        const uint32_t* UBh = (const uint32_t*)(S + 2 * TILE_BF);
        const uint32_t* UBl = (const uint32_t*)(S + 3 * TILE_BF);

#pragma unroll
        for (int ks = 0; ks < 2; ks++) {
            const int kw = ks * 8 + tig;
            uint32_t ah[4][4], al[4][4];
#pragma unroll
            for (int mi = 0; mi < 4; mi++) {
                int r = wm * 64 + mi * 16 + g;
                ah[mi][0] = UAh[r * LDW + kw];
                ah[mi][1] = UAh[(r + 8) * LDW + kw];
                ah[mi][2] = UAh[r * LDW + kw + 4];
                ah[mi][3] = UAh[(r + 8) * LDW + kw + 4];
                al[mi][0] = UAl[r * LDW + kw];
                al[mi][1] = UAl[(r + 8) * LDW + kw];
                al[mi][2] = UAl[r * LDW + kw + 4];
                al[mi][3] = UAl[(r + 8) * LDW + kw + 4];
            }
            uint32_t bh[4][2], bl[4][2];
#pragma unroll
            for (int ni = 0; ni < 4; ni++) {
                int cc = wn * 32 + ni * 8 + g;
                bh[ni][0] = UBh[cc * LDW + kw];
                bh[ni][1] = UBh[cc * LDW + kw + 4];
                bl[ni][0] = UBl[cc * LDW + kw];
                bl[ni][1] = UBl[cc * LDW + kw + 4];
            }
#pragma unroll
            for (int mi = 0; mi < 4; mi++)
#pragma unroll
                for (int ni = 0; ni < 4; ni++) {
                    MMA16816(acc[mi][ni], ah[mi], bh[ni]);
                    MMA16816(acc[mi][ni], ah[mi], bl[ni]);
                    MMA16816(acc[mi][ni], al[mi], bh[ni]);
                }
        }
        __syncthreads();
    }

    // epilogue
#pragma unroll
    for (int mi = 0; mi < 4; mi++) {
#pragma unroll
        for (int ni = 0; ni < 4; ni++) {
            int r1 = row0 + wm * 64 + mi * 16 + g;
            int c  = col0 + wn * 32 + ni * 8 + 2 * tig;
            float v00 = acc[mi][ni][0] + bias[c];
            float v01 = acc[mi][ni][1] + bias[c + 1];
            float v10 = acc[mi][ni][2] + bias[c];
            float v11 = acc[mi][ni][3] + bias[c + 1];
            if (mode <= 2) {
                int hd = c >> 6;
                int dd = c & 63;
#pragma unroll
                for (int rr = 0; rr < 2; rr++) {
                    int r  = r1 + rr * 8;
                    int b_ = r >> 11;
                    int s_ = r & (SEQ - 1);
                    float x0 = rr ? v10 : v00;
                    float x1 = rr ? v11 : v01;
                    __nv_bfloat162 hi2 = __floats2bfloat162_rn(x0, x1);
                    float l0 = x0 - __bfloat162float(hi2.x);
                    float l1 = x1 - __bfloat162float(hi2.y);
                    __nv_bfloat162 lo2 = __floats2bfloat162_rn(l0, l1);
                    int bhn = (b_ << 4) + hd;
                    if (mode == 2) {
                        size_t base = ((size_t)bhn * DEPTH + dd) * SEQ + s_;
                        g_vth[base]       = hi2.x;
                        g_vtl[base]       = lo2.x;
                        g_vth[base + SEQ] = hi2.y;
                        g_vtl[base + SEQ] = lo2.y;
                    } else {
                        size_t base = ((size_t)bhn * SEQ + s_) * DEPTH + dd;
                        __nv_bfloat16* Ph = (mode == 0) ? g_qhh : g_khh;
                        __nv_bfloat16* Pl = (mode == 0) ? g_qhl : g_khl;
                        *(__nv_bfloat162*)(Ph + base) = hi2;
                        *(__nv_bfloat162*)(Pl + base) = lo2;
                    }
                }
            } else {
                Yext[(size_t)r1 * D_MODEL + c]           = v00;
                Yext[(size_t)r1 * D_MODEL + c + 1]       = v01;
                Yext[(size_t)(r1 + 8) * D_MODEL + c]     = v10;
                Yext[(size_t)(r1 + 8) * D_MODEL + c + 1] = v11;
            }
        }
    }
}

// ============================================================
// Tensor-core flash attention (split bf16, FA2 register dataflow)
// 128 threads = 4 warps, 64 queries/block, 64-key tiles, cp.async 2-stage.
// ============================================================
#define AT_STR   36                        // words per row (64 bf16 + 8 pad)
#define AT_TILE  (64*AT_STR)               // 2304 words
#define AT_KH    0
#define AT_KL    AT_TILE
#define AT_VH    (2*AT_TILE)
#define AT_VL    (3*AT_TILE)
#define AT_MASK  (4*AT_TILE)               // 1024 words (64x64 bytes)
#define AT_STAGE (4*AT_TILE + 1024)        // 10240 words
#define AT_QH    (2*AT_STAGE)              // 20480
#define AT_QL    (2*AT_STAGE + AT_TILE)
#define AT_SMEM  ((2*AT_STAGE + 2*AT_TILE) * 4)   // 100352 bytes

__device__ __forceinline__ void at_load_kv(uint32_t* sw, int sb,
    const __nv_bfloat16* khh, const __nv_bfloat16* khl,
    const __nv_bfloat16* vth, const __nv_bfloat16* vtl,
    const unsigned char* mb, int i0, int j0, int tid)
{
#pragma unroll
    for (int it = 0; it < 4; it++) {
        int c   = tid + it * 128;       // 0..511
        int row = c >> 3;
        int seg = c & 7;
        int w   = sb + row * AT_STR + seg * 4;
        cpa16(s2u(sw + w + AT_KH), khh + (j0 + row) * DEPTH + seg * 8);
        cpa16(s2u(sw + w + AT_KL), khl + (j0 + row) * DEPTH + seg * 8);
        cpa16(s2u(sw + w + AT_VH), vth + (size_t)row * SEQ + j0 + seg * 8);
        cpa16(s2u(sw + w + AT_VL), vtl + (size_t)row * SEQ + j0 + seg * 8);
    }
    {
        int c   = tid;                  // 0..127 then +128
#pragma unroll
        for (int it = 0; it < 2; it++) {
            int cc  = c + it * 128;     // 0..255
            int row = cc >> 2;
            int seg = cc & 3;
            cpa16(s2u(sw + sb + AT_MASK + row * 16 + seg * 4),
                  mb + (size_t)(i0 + row) * SEQ + j0 + seg * 16);
        }
    }
    asm volatile("cp.async.commit_group;\n" ::: "memory");
}

__device__ __forceinline__ void split2(float f0, float f1,
                                       uint32_t& hi, uint32_t& lo)
{
    __nv_bfloat162 h2 = __floats2bfloat162_rn(f0, f1);
    float r0 = f0 - __bfloat162float(h2.x);
    float r1 = f1 - __bfloat162float(h2.y);
    __nv_bfloat162 l2 = __floats2bfloat162_rn(r0, r1);
    hi = *(uint32_t*)&h2;
    lo = *(uint32_t*)&l2;
}

__global__ __launch_bounds__(128) void attn_flash_tc(const unsigned char* __restrict__ mask)
{
    extern __shared__ uint32_t sw[];

    const int bh  = blockIdx.y;
    const int b_  = bh >> 4;
    const int hd  = bh & 15;
    const int qt  = gridDim.x - 1 - blockIdx.x;   // heavy-first
    const int i0  = qt * 64;
    const int tid = threadIdx.x;
    const int lane = tid & 31;
    const int warp = tid >> 5;
    const int g    = lane >> 2;
    const int t4   = lane & 3;

    const __nv_bfloat16* qhh = g_qhh + (size_t)bh * SEQ * DEPTH + (size_t)i0 * DEPTH;
    const __nv_bfloat16* qhl = g_qhl + (size_t)bh * SEQ * DEPTH + (size_t)i0 * DEPTH;
    const __nv_bfloat16* khh = g_khh + (size_t)bh * SEQ * DEPTH;
    const __nv_bfloat16* khl = g_khl + (size_t)bh * SEQ * DEPTH;
    const __nv_bfloat16* vth = g_vth + (size_t)bh * DEPTH * SEQ;
    const __nv_bfloat16* vtl = g_vtl + (size_t)bh * DEPTH * SEQ;
    const unsigned char* mb  = mask + (size_t)b_ * SEQ * SEQ;

    // ---- group 0: Q tile (hi+lo) ----
#pragma unroll
    for (int it = 0; it < 4; it++) {
        int c   = tid + it * 128;
        int row = c >> 3;
        int seg = c & 7;
        int w   = row * AT_STR + seg * 4;
        cpa16(s2u(sw + AT_QH + w), qhh + row * DEPTH + seg * 8);
        cpa16(s2u(sw + AT_QL + w), qhl + row * DEPTH + seg * 8);
    }
    asm volatile("cp.async.commit_group;\n" ::: "memory");

    // ---- group 1: tile 0 ----
    at_load_kv(sw, 0, khh, khl, vth, vtl, mb, i0, 0, tid);

    asm volatile("cp.async.wait_group 1;\n" ::: "memory");   // Q ready
    __syncthreads();

    // Q fragments (register resident)
    const int rA = warp * 16 + g;
    const int rB = rA + 8;
    uint32_t qh[4][4], ql[4][4];
#pragma unroll
    for (int ks = 0; ks < 4; ks++) {
        int w0 = 8 * ks + t4;
        qh[ks][0] = sw[AT_QH + rA * AT_STR + w0];
        qh[ks][1] = sw[AT_QH + rB * AT_STR + w0];
        qh[ks][2] = sw[AT_QH + rA * AT_STR + w0 + 4];
        qh[ks][3] = sw[AT_QH + rB * AT_STR + w0 + 4];
        ql[ks][0] = sw[AT_QL + rA * AT_STR + w0];
        ql[ks][1] = sw[AT_QL + rB * AT_STR + w0];
        ql[ks][2] = sw[AT_QL + rA * AT_STR + w0 + 4];
        ql[ks][3] = sw[AT_QL + rB * AT_STR + w0 + 4];
    }

    float oc[8][4];
#pragma unroll
    for (int dt = 0; dt < 8; dt++)
#pragma unroll
        for (int c = 0; c < 4; c++) oc[dt][c] = 0.f;
    float m_a = -CUDART_INF_F, m_b = -CUDART_INF_F;
    float l_a = 0.f, l_b = 0.f;

    const int iga = i0 + rA;
    const int igb = i0 + rB;
    const int ntiles = qt + 1;

    for (int t = 0; t < ntiles; t++) {
        const int j0 = t * 64;
        if (t + 1 < ntiles)
            at_load_kv(sw, ((t + 1) & 1) * AT_STAGE, khh, khl, vth, vtl,
                       mb, i0, (t + 1) * 64, tid);
        if (t + 1 < ntiles) asm volatile("cp.async.wait_group 1;\n" ::: "memory");
        else                asm volatile("cp.async.wait_group 0;\n" ::: "memory");
        __syncthreads();

        const int sb = (t & 1) * AT_STAGE;
        const uint32_t* KH = sw + sb + AT_KH;
        const uint32_t* KL = sw + sb + AT_KL;
        const uint32_t* VH = sw + sb + AT_VH;
        const uint32_t* VL = sw + sb + AT_VL;
        const unsigned char* Mt = (const unsigned char*)(sw + sb + AT_MASK);

        // S = Q K^T  (3-term split)
        float sc[8][4];
#pragma unroll
        for (int nt = 0; nt < 8; nt++)
#pragma unroll
            for (int c = 0; c < 4; c++) sc[nt][c] = 0.f;
#pragma unroll
        for (int ks = 0; ks < 4; ks++) {
#pragma unroll
            for (int nt = 0; nt < 8; nt++) {
                int wo = (nt * 8 + g) * AT_STR + 8 * ks + t4;
                uint32_t kbh[2] = { KH[wo], KH[wo + 4] };
                uint32_t kbl[2] = { KL[wo], KL[wo + 4] };
                MMA16816(sc[nt], qh[ks], kbh);
                MMA16816(sc[nt], qh[ks], kbl);
                MMA16816(sc[nt], ql[ks], kbh);
            }
        }

        // scale + RPE + mask, row maxima
        float mxa = -CUDART_INF_F, mxb = -CUDART_INF_F;
        const int rla = warp * 16 + g;
        const int rlb = rla + 8;
#pragma unroll
        for (int nt = 0; nt < 8; nt++) {
#pragma unroll
            for (int cc = 0; cc < 2; cc++) {
                int jl = nt * 8 + 2 * t4 + cc;
                int jg = j0 + jl;
                float va = sc[nt][cc] * 0.125f + (float)(jg - iga);
                if (jg > iga || Mt[rla * 64 + jl]) va = -1e9f;
                sc[nt][cc] = va;
                mxa = fmaxf(mxa, va);
                float vb = sc[nt][cc + 2] * 0.125f + (float)(jg - igb);
                if (jg > igb || Mt[rlb * 64 + jl]) vb = -1e9f;
                sc[nt][cc + 2] = vb;
                mxb = fmaxf(mxb, vb);
            }
        }
        mxa = fmaxf(mxa, __shfl_xor_sync(0xffffffffu, mxa, 1));
        mxa = fmaxf(mxa, __shfl_xor_sync(0xffffffffu, mxa, 2));
        mxb = fmaxf(mxb, __shfl_xor_sync(0xffffffffu, mxb, 1));
        mxb = fmaxf(mxb, __shfl_xor_sync(0xffffffffu, mxb, 2));

        float mna = fmaxf(m_a, mxa);
        float mnb = fmaxf(m_b, mxb);
        float ala = __expf(m_a - mna);
        float alb = __expf(m_b - mnb);
        m_a = mna; m_b = mnb;

        float sa = 0.f, sb2 = 0.f;
#pragma unroll
        for (int nt = 0; nt < 8; nt++) {
#pragma unroll
            for (int cc = 0; cc < 2; cc++) {
                float pa = __expf(sc[nt][cc] - mna);
                sc[nt][cc] = pa; sa += pa;
                float pb = __expf(sc[nt][cc + 2] - mnb);
                sc[nt][cc + 2] = pb; sb2 += pb;
            }
        }
        sa  += __shfl_xor_sync(0xffffffffu, sa, 1);
        sa  += __shfl_xor_sync(0xffffffffu, sa, 2);
        sb2 += __shfl_xor_sync(0xffffffffu, sb2, 1);
        sb2 += __shfl_xor_sync(0xffffffffu, sb2, 2);
        l_a = l_a * ala + sa;
        l_b = l_b * alb + sb2;

#pragma unroll
        for (int dt = 0; dt < 8; dt++) {
            oc[dt][0] *= ala; oc[dt][1] *= ala;
            oc[dt][2] *= alb; oc[dt][3] *= alb;
        }

        // P -> bf16-split A fragments (pure register permutation)
        uint32_t pah[4][4], pal[4][4];
#pragma unroll
        for (int kt = 0; kt < 4; kt++) {
            split2(sc[2*kt][0],     sc[2*kt][1],     pah[kt][0], pal[kt][0]);
            split2(sc[2*kt][2],     sc[2*kt][3],     pah[kt][1], pal[kt][1]);
            split2(sc[2*kt+1][0],   sc[2*kt+1][1],   pah[kt][2], pal[kt][2]);
            split2(sc[2*kt+1][2],   sc[2*kt+1][3],   pah[kt][3], pal[kt][3]);
        }

        // O += P V  (3-term split); V^T in smem [d][key]
#pragma unroll
        for (int kt = 0; kt < 4; kt++) {
#pragma unroll
            for (int dt = 0; dt < 8; dt++) {
                int wo = (dt * 8 + g) * AT_STR + 8 * kt + t4;
                uint32_t vbh[2] = { VH[wo], VH[wo + 4] };
                uint32_t vbl[2] = { VL[wo], VL[wo + 4] };
                MMA16816(oc[dt], pah[kt], vbh);
                MMA16816(oc[dt], pah[kt], vbl);
                MMA16816(oc[dt], pal[kt], vbh);
            }
        }
        __syncthreads();
    }

    // epilogue: normalize, write bf16-split ctx directly (GEMM A layout)
    float inva = 1.0f / l_a;
    float invb = 1.0f / l_b;
    const size_t rowA = (size_t)(b_ * SEQ + iga) * D_MODEL;
    const size_t rowB = (size_t)(b_ * SEQ + igb) * D_MODEL;
#pragma unroll
    for (int dt = 0; dt < 8; dt++) {
        int col = hd * 64 + dt * 8 + 2 * t4;
        uint32_t h0, l0;
        split2(oc[dt][0] * inva, oc[dt][1] * inva, h0, l0);
        *(uint32_t*)(g_ah + rowA + col) = h0;
        *(uint32_t*)(g_al + rowA + col) = l0;
        uint32_t h1, l1;
        split2(oc[dt][2] * invb, oc[dt][3] * invb, h1, l1);
        *(uint32_t*)(g_ah + rowB + col) = h1;
        *(uint32_t*)(g_al + rowB + col) = l1;
    }
    if (t4 == 0) {
        g_m[(size_t)bh * SEQ + iga] = m_a;
        g_l[(size_t)bh * SEQ + iga] = l_a;
        g_m[(size_t)bh * SEQ + igb] = m_b;
        g_l[(size_t)bh * SEQ + igb] = l_b;
    }
}

// ============================================================
// Optional full attention probabilities (fp32 SIMT, Q/K rebuilt from splits)
// ============================================================
#define QS_STR 65

__global__ void attn_probs(const unsigned char* __restrict__ mask,
                           float* __restrict__ attn)
{
    __shared__ float Qs[64 * QS_STR];
    __shared__ float Ks[64 * QS_STR];
    __shared__ unsigned char Ms[64 * 64];

    const int bh = blockIdx.y;
    const int b_ = bh >> 4;
    const int qt = blockIdx.x;
    const int i0 = qt * 64;

    const int tid = threadIdx.x;
    const int tx  = tid & 15;
    const int ty  = tid >> 4;
    const int r0  = ty * 4;
    const int c0  = tx * 4;

    const __nv_bfloat16* qhh = g_qhh + (size_t)bh * SEQ * DEPTH;
    const __nv_bfloat16* qhl = g_qhl + (size_t)bh * SEQ * DEPTH;
    const __nv_bfloat16* khh = g_khh + (size_t)bh * SEQ * DEPTH;
    const __nv_bfloat16* khl = g_khl + (size_t)bh * SEQ * DEPTH;
    const unsigned char* mb  = mask + (size_t)b_ * SEQ * SEQ;

    for (int idx = tid; idx < 4096; idx += 256) {
        int r = idx >> 6;
        int c = idx & 63;
        size_t go = (size_t)(i0 + r) * DEPTH + c;
        Qs[r * QS_STR + c] = __bfloat162float(qhh[go]) + __bfloat162float(qhl[go]);
    }

    float mi[4], li[4];
#pragma unroll
    for (int i = 0; i < 4; i++) {
        mi[i] = g_m[(size_t)bh * SEQ + i0 + r0 + i];
        li[i] = 1.0f / g_l[(size_t)bh * SEQ + i0 + r0 + i];
    }
    __syncthreads();

    for (int jt = 0; jt < SEQ / 64; jt++) {
        const int j0 = jt * 64;
        if (j0 > i0 + 63) {
            for (int idx = tid; idx < 1024; idx += 256) {
                int r  = idx >> 4;
                int c4 = (idx & 15) << 2;
                float4 z = {0.f, 0.f, 0.f, 0.f};
                *(float4*)(attn + ((size_t)bh * SEQ + i0 + r) * SEQ + j0 + c4) = z;
            }
            continue;
        }
        for (int idx = tid; idx < 4096; idx += 256) {
            int r = idx >> 6;
            int c = idx & 63;
            size_t go = (size_t)(j0 + r) * DEPTH + c;
            Ks[r * QS_STR + c] = __bfloat162float(khh[go]) + __bfloat162float(khl[go]);
        }
        {
            int r   = tid >> 2;
            int c16 = (tid & 3) << 4;
            *(uint4*)(Ms + r * 64 + c16) =
                *(const uint4*)(mb + (size_t)(i0 + r) * SEQ + j0 + c16);
        }
        __syncthreads();

        float s[4][4];
#pragma unroll
        for (int i = 0; i < 4; i++)
#pragma unroll
            for (int j = 0; j < 4; j++) s[i][j] = 0.f;
#pragma unroll 16
        for (int k = 0; k < 64; k++) {
            float a[4], b[4];
#pragma unroll
            for (int i = 0; i < 4; i++) a[i] = Qs[(r0 + i) * QS_STR + k];
#pragma unroll
            for (int j = 0; j < 4; j++) b[j] = Ks[(c0 + j) * QS_STR + k];
#pragma unroll
            for (int i = 0; i < 4; i++)
#pragma unroll
                for (int j = 0; j < 4; j++)
                    s[i][j] += a[i] * b[j];
        }

#pragma unroll
        for (int i = 0; i < 4; i++) {
            int ig = i0 + r0 + i;
            float4 ov;
            float* pv = (float*)&ov;
#pragma unroll
            for (int j = 0; j < 4; j++) {
                int jg = j0 + c0 + j;
                float sv = s[i][j] * 0.125f + (float)(jg - ig);
                bool bad = (jg > ig) || Ms[(r0 + i) * 64 + (c0 + j)];
                pv[j] = bad ? 0.f : __expf(sv - mi[i]) * li[i];
            }
            *(float4*)(attn + ((size_t)bh * SEQ + ig) * SEQ + j0 + c0) = ov;
        }
        __syncthreads();
    }
}

// ============================================================
extern "C" void kernel_launch(void* const* d_in, const int* in_sizes, int n_in,
                              void* d_out, int out_size)
{
    const float* q  = (const float*)d_in[0];
    const float* k  = (const float*)d_in[1];
    const float* v  = (const float*)d_in[2];
    const float* Wq = (const float*)d_in[3];
    const float* bq = (const float*)d_in[4];
    const float* Wk = (const float*)d_in[5];
    const float* bk = (const float*)d_in[6];
    const float* Wv = (const float*)d_in[7];
    const float* bv = (const float*)d_in[8];
    const float* Wo = (const float*)d_in[9];
    const float* bo = (const float*)d_in[10];
    const unsigned char* mask = (const unsigned char*)d_in[11];

    float* out = (float*)d_out;
    const long long OUT_ELEMS = (long long)BATCH * SEQ * D_MODEL;
    const int writeAttn = ((long long)out_size > OUT_ELEMS) ? 1 : 0;
    float* attn_out = out + OUT_ELEMS;

    cudaFuncSetAttribute(gemm_mma,
                         cudaFuncAttributeMaxDynamicSharedMemorySize, GEMM_SMEM);
    cudaFuncSetAttribute(attn_flash_tc,
                         cudaFuncAttributeMaxDynamicSharedMemorySize, AT_SMEM);

    const int NX = M_ROWS * D_MODEL;
    dim3 gg(D_MODEL / 128, M_ROWS / 128);   // (8, 32)

    cvt_wT<<<4096, 256>>>(Wq);
    cvt_x<<<2048, 256>>>(q, NX);
    gemm_mma<<<gg, 256, GEMM_SMEM>>>(bq, nullptr, 0);

    cvt_wT<<<4096, 256>>>(Wk);
    cvt_x<<<2048, 256>>>(k, NX);
    gemm_mma<<<gg, 256, GEMM_SMEM>>>(bk, nullptr, 1);

    cvt_wT<<<4096, 256>>>(Wv);
    cvt_x<<<2048, 256>>>(v, NX);
    gemm_mma<<<gg, 256, GEMM_SMEM>>>(bv, nullptr, 2);

    attn_flash_tc<<<dim3(SEQ / 64, BH), 128, AT_SMEM>>>(mask);

    if (writeAttn)
        attn_probs<<<dim3(SEQ / 64, BH), 256>>>(mask, attn_out);

    cvt_wT<<<4096, 256>>>(Wo);
    gemm_mma<<<gg, 256, GEMM_SMEM>>>(bo, out, 3);
}

// round 5
// speedup vs baseline: 5.5027x; 1.1059x over previous
#include <cuda_runtime.h>
#include <cuda_bf16.h>
#include <math_constants.h>
#include <cstdint>

// Problem constants
#define D_MODEL   1024
#define NUM_HEADS 16
#define DEPTH     64
#define BATCH     2
#define SEQ       2048
#define BH        (BATCH*NUM_HEADS)     // 32
#define M_ROWS    (BATCH*SEQ)           // 4096
#define NX        (M_ROWS*D_MODEL)      // 4M

// -------- device scratch --------
__device__ float g_m[BH*SEQ];
__device__ float g_l[BH*SEQ];
__device__ __align__(16) __nv_bfloat16 g_ah[NX];          // ctx hi (GEMM A, mode 3)
__device__ __align__(16) __nv_bfloat16 g_al[NX];          // ctx lo
__device__ __align__(16) __nv_bfloat16 g_xh[3*NX];        // q,k,v inputs hi
__device__ __align__(16) __nv_bfloat16 g_xl[3*NX];        // q,k,v inputs lo
__device__ __align__(16) __nv_bfloat16 g_wth[4*D_MODEL*D_MODEL]; // W^T hi (q,k,v,o)
__device__ __align__(16) __nv_bfloat16 g_wtl[4*D_MODEL*D_MODEL]; // W^T lo
__device__ __align__(16) __nv_bfloat16 g_qhh[BH*SEQ*DEPTH];
__device__ __align__(16) __nv_bfloat16 g_qhl[BH*SEQ*DEPTH];
__device__ __align__(16) __nv_bfloat16 g_khh[BH*SEQ*DEPTH];
__device__ __align__(16) __nv_bfloat16 g_khl[BH*SEQ*DEPTH];
__device__ __align__(16) __nv_bfloat16 g_vth[BH*DEPTH*SEQ];   // V^T [bh][d][s]
__device__ __align__(16) __nv_bfloat16 g_vtl[BH*DEPTH*SEQ];

static __device__ __forceinline__ uint32_t s2u(const void* p) {
    return static_cast<uint32_t>(__cvta_generic_to_shared(p));
}
static __device__ __forceinline__ void cpa16(uint32_t s, const void* g) {
    asm volatile("cp.async.cg.shared.global [%0], [%1], 16;\n" :: "r"(s), "l"(g));
}

#define LDSM_X4(d0,d1,d2,d3,addr) asm volatile( \
    "ldmatrix.sync.aligned.m8n8.x4.shared.b16 {%0,%1,%2,%3}, [%4];" \
    : "=r"(d0),"=r"(d1),"=r"(d2),"=r"(d3) : "r"(addr))

#define MMA16816(d, a, b) asm volatile( \
    "mma.sync.aligned.m16n8k16.row.col.f32.bf16.bf16.f32 " \
    "{%0,%1,%2,%3}, {%4,%5,%6,%7}, {%8,%9}, {%0,%1,%2,%3};" \
    : "+f"(d[0]), "+f"(d[1]), "+f"(d[2]), "+f"(d[3]) \
    : "r"(a[0]), "r"(a[1]), "r"(a[2]), "r"(a[3]), "r"(b[0]), "r"(b[1]))

__device__ __forceinline__ void split2(float f0, float f1,
                                       uint32_t& hi, uint32_t& lo)
{
    __nv_bfloat162 h2 = __floats2bfloat162_rn(f0, f1);
    float r0 = f0 - __bfloat162float(h2.x);
    float r1 = f1 - __bfloat162float(h2.y);
    __nv_bfloat162 l2 = __floats2bfloat162_rn(r0, r1);
    hi = *(uint32_t*)&h2;
    lo = *(uint32_t*)&l2;
}

// ============================================================
// cvt_w4: all four weights, tiled transpose, coalesced writes
// W[k][n] fp32 -> g_wth/g_wtl [z][n][k] bf16
// ============================================================
__global__ void cvt_w4(const float* __restrict__ Wq, const float* __restrict__ Wk,
                       const float* __restrict__ Wv, const float* __restrict__ Wo)
{
    __shared__ float t[32][33];
    const int z = blockIdx.z;
    const float* W = (z == 0) ? Wq : (z == 1) ? Wk : (z == 2) ? Wv : Wo;
    __nv_bfloat16* oh = g_wth + (size_t)z * D_MODEL * D_MODEL;
    __nv_bfloat16* ol = g_wtl + (size_t)z * D_MODEL * D_MODEL;
    const int k0 = blockIdx.y * 32, n0 = blockIdx.x * 32;
    const int tid = threadIdx.x;
    const int tr = tid >> 5, tc = tid & 31;
#pragma unroll
    for (int i = 0; i < 4; i++)
        t[tr + i * 8][tc] = W[(size_t)(k0 + tr + i * 8) * D_MODEL + n0 + tc];
    __syncthreads();
    const int wr = tid >> 4;           // 0..15 (n-row)
    const int wc = (tid & 15) * 2;     // 0..30 (k-pair)
#pragma unroll
    for (int i = 0; i < 2; i++) {
        int n = wr + i * 16;
        float x0 = t[wc][n], x1 = t[wc + 1][n];
        uint32_t hi, lo;
        split2(x0, x1, hi, lo);
        *(uint32_t*)(oh + (size_t)(n0 + n) * D_MODEL + k0 + wc) = hi;
        *(uint32_t*)(ol + (size_t)(n0 + n) * D_MODEL + k0 + wc) = lo;
    }
}

// ============================================================
// cvt_x3: q,k,v fp32 -> bf16 hi/lo split (linear layout)
// ============================================================
__global__ void cvt_x3(const float* __restrict__ q, const float* __restrict__ k,
                       const float* __restrict__ v)
{
    const int z = blockIdx.z;
    const float* src = (z == 0) ? q : (z == 1) ? k : v;
    __nv_bfloat16* oh = g_xh + (size_t)z * NX;
    __nv_bfloat16* ol = g_xl + (size_t)z * NX;
    for (int i = blockIdx.x * 256 + threadIdx.x; i < NX / 4; i += 2048 * 256) {
        float4 x = ((const float4*)src)[i];
        uint32_t h0, l0, h1, l1;
        split2(x.x, x.y, h0, l0);
        split2(x.z, x.w, h1, l1);
        uint2 hh = {h0, h1}, ll = {l0, l1};
        *(uint2*)(oh + (size_t)i * 4) = hh;
        *(uint2*)(ol + (size_t)i * 4) = ll;
    }
}

// ============================================================
// bf16-split tensor-core GEMM with ldmatrix fragments
// grid.z selects projection for fused QKV launch.
// mode 0: Q -> g_qhh/l ; 1: K -> g_khh/l ; 2: V -> g_vth/l (transposed)
// mode 3: ctx @ Wo -> fp32 Yext
// ============================================================
#define LDT      40
#define TILE_BF  (128*LDT)
#define STAGE_BF (4*TILE_BF)
#define GEMM_SMEM (2*STAGE_BF*2)

__device__ __forceinline__ void load_stage(__nv_bfloat16* S,
    const __nv_bfloat16* gAh, const __nv_bfloat16* gAl,
    const __nv_bfloat16* gBh, const __nv_bfloat16* gBl,
    int k0, int tid)
{
#pragma unroll
    for (int r = 0; r < 2; r++) {
        int c   = tid + 256 * r;
        int row = c >> 2;
        int seg = c & 3;
        int go  = row * D_MODEL + k0 + seg * 8;
        int so  = row * LDT + seg * 8;
        cpa16(s2u(S + so),               gAh + go);
        cpa16(s2u(S + TILE_BF + so),     gAl + go);
        cpa16(s2u(S + 2 * TILE_BF + so), gBh + go);
        cpa16(s2u(S + 3 * TILE_BF + so), gBl + go);
    }
    asm volatile("cp.async.commit_group;\n" ::: "memory");
}

__global__ __launch_bounds__(256) void gemm_mma(const float* __restrict__ bias0,
                                                const float* __restrict__ bias1,
                                                const float* __restrict__ bias2,
                                                float* __restrict__ Yext,
                                                int baseMode)
{
    extern __shared__ __nv_bfloat16 sm[];

    const int z    = blockIdx.z;
    const int mode = (baseMode == 3) ? 3 : z;
    const int wz   = (baseMode == 3) ? 3 : z;
    const float* bias = (mode == 1) ? bias1 : (mode == 2) ? bias2 : bias0;

    const int tid  = threadIdx.x;
    const int lane = tid & 31;
    const int warp = tid >> 5;
    const int wm   = warp >> 2;
    const int wn   = warp & 3;
    const int g    = lane >> 2;
    const int tig  = lane & 3;
    const int row0 = blockIdx.y * 128;
    const int col0 = blockIdx.x * 128;

    const __nv_bfloat16* srcAh = (mode == 3) ? g_ah : (g_xh + (size_t)z * NX);
    const __nv_bfloat16* srcAl = (mode == 3) ? g_al : (g_xl + (size_t)z * NX);
    const __nv_bfloat16* gAh = srcAh + (size_t)row0 * D_MODEL;
    const __nv_bfloat16* gAl = srcAl + (size_t)row0 * D_MODEL;
    const __nv_bfloat16* gBh = g_wth + (size_t)wz * D_MODEL * D_MODEL + (size_t)col0 * D_MODEL;
    const __nv_bfloat16* gBl = g_wtl + (size_t)wz * D_MODEL * D_MODEL + (size_t)col0 * D_MODEL;

    // ldmatrix per-lane addressing
    const int aRow = lane & 15;
    const int aK   = (lane >> 4) * 8;          // bf16 units
    const int bgrp = lane >> 3;
    const int bRow = (lane & 7) + ((bgrp >> 1) ? 8 : 0);
    const int bK   = (bgrp & 1) * 8;

    float acc[4][4][4];
#pragma unroll
    for (int mi = 0; mi < 4; mi++)
#pragma unroll
        for (int ni = 0; ni < 4; ni++)
#pragma unroll
            for (int r = 0; r < 4; r++) acc[mi][ni][r] = 0.f;

    load_stage(sm, gAh, gAl, gBh, gBl, 0, tid);

    const uint32_t smb = s2u(sm);
    const int NT = D_MODEL / 32;
    for (int t = 0; t < NT; t++) {
        if (t + 1 < NT)
            load_stage(sm + ((t + 1) & 1) * STAGE_BF, gAh, gAl, gBh, gBl,
                       (t + 1) * 32, tid);
        if (t + 1 < NT) asm volatile("cp.async.wait_group 1;\n" ::: "memory");
        else            asm volatile("cp.async.wait_group 0;\n" ::: "memory");
        __syncthreads();

        const uint32_t stb = smb + (uint32_t)((t & 1) * STAGE_BF) * 2;
        const uint32_t AHb = stb;
        const uint32_t ALb = stb + TILE_BF * 2;
        const uint32_t BHb = stb + 2 * TILE_BF * 2;
        const uint32_t BLb = stb + 3 * TILE_BF * 2;

#pragma unroll
        for (int ks = 0; ks < 2; ks++) {
            uint32_t ah[4][4], al[4][4];
#pragma unroll
            for (int mi = 0; mi < 4; mi++) {
                uint32_t off = (uint32_t)(((wm * 64 + mi * 16 + aRow) * LDT
                                           + ks * 16 + aK) * 2);
                LDSM_X4(ah[mi][0], ah[mi][1], ah[mi][2], ah[mi][3], AHb + off);
                LDSM_X4(al[mi][0], al[mi][1], al[mi][2], al[mi][3], ALb + off);
            }
            uint32_t bh[4][2], bl[4][2];
#pragma unroll
            for (int np = 0; np < 2; np++) {
                uint32_t off = (uint32_t)(((wn * 32 + np * 16 + bRow) * LDT
                                           + ks * 16 + bK) * 2);
                LDSM_X4(bh[2*np][0], bh[2*np][1], bh[2*np+1][0], bh[2*np+1][1],
                        BHb + off);
                LDSM_X4(bl[2*np][0], bl[2*np][1], bl[2*np+1][0], bl[2*np+1][1],
                        BLb + off);
            }
#pragma unroll
            for (int mi = 0; mi < 4; mi++)
#pragma unroll
                for (int ni = 0; ni < 4; ni++) {
                    MMA16816(acc[mi][ni], ah[mi], bh[ni]);
                    MMA16816(acc[mi][ni], ah[mi], bl[ni]);
                    MMA16816(acc[mi][ni], al[mi], bh[ni]);
                }
        }
        __syncthreads();
    }

    // epilogue
#pragma unroll
    for (int mi = 0; mi < 4; mi++) {
#pragma unroll
        for (int ni = 0; ni < 4; ni++) {
            int r1 = row0 + wm * 64 + mi * 16 + g;
            int c  = col0 + wn * 32 + ni * 8 + 2 * tig;
            float v00 = acc[mi][ni][0] + bias[c];
            float v01 = acc[mi][ni][1] + bias[c + 1];
            float v10 = acc[mi][ni][2] + bias[c];
            float v11 = acc[mi][ni][3] + bias[c + 1];
            if (mode <= 2) {
                int hd = c >> 6;
                int dd = c & 63;
#pragma unroll
                for (int rr = 0; rr < 2; rr++) {
                    int r  = r1 + rr * 8;
                    int b_ = r >> 11;
                    int s_ = r & (SEQ - 1);
                    float x0 = rr ? v10 : v00;
                    float x1 = rr ? v11 : v01;
                    uint32_t hi, lo;
                    split2(x0, x1, hi, lo);
                    __nv_bfloat162 hi2 = *(__nv_bfloat162*)&hi;
                    __nv_bfloat162 lo2 = *(__nv_bfloat162*)&lo;
                    int bhn = (b_ << 4) + hd;
                    if (mode == 2) {
                        size_t base = ((size_t)bhn * DEPTH + dd) * SEQ + s_;
                        g_vth[base]       = hi2.x;
                        g_vtl[base]       = lo2.x;
                        g_vth[base + SEQ] = hi2.y;
                        g_vtl[base + SEQ] = lo2.y;
                    } else {
                        size_t base = ((size_t)bhn * SEQ + s_) * DEPTH + dd;
                        __nv_bfloat16* Ph = (mode == 0) ? g_qhh : g_khh;
                        __nv_bfloat16* Pl = (mode == 0) ? g_qhl : g_khl;
                        *(uint32_t*)(Ph + base) = hi;
                        *(uint32_t*)(Pl + base) = lo;
                    }
                }
            } else {
                Yext[(size_t)r1 * D_MODEL + c]           = v00;
                Yext[(size_t)r1 * D_MODEL + c + 1]       = v01;
                Yext[(size_t)(r1 + 8) * D_MODEL + c]     = v10;
                Yext[(size_t)(r1 + 8) * D_MODEL + c + 1] = v11;
            }
        }
    }
}

// ============================================================
// Tensor-core flash attention (split bf16, ldmatrix fragments)
// ============================================================
#define AT_STR   36
#define AT_TILE  (64*AT_STR)
#define AT_KH    0
#define AT_KL    AT_TILE
#define AT_VH    (2*AT_TILE)
#define AT_VL    (3*AT_TILE)
#define AT_MASK  (4*AT_TILE)
#define AT_STAGE (4*AT_TILE + 1024)
#define AT_QH    (2*AT_STAGE)
#define AT_QL    (2*AT_STAGE + AT_TILE)
#define AT_SMEM  ((2*AT_STAGE + 2*AT_TILE) * 4)

__device__ __forceinline__ void at_load_kv(uint32_t* sw, int sb,
    const __nv_bfloat16* khh, const __nv_bfloat16* khl,
    const __nv_bfloat16* vth, const __nv_bfloat16* vtl,
    const unsigned char* mb, int i0, int j0, int tid)
{
#pragma unroll
    for (int it = 0; it < 4; it++) {
        int c   = tid + it * 128;
        int row = c >> 3;
        int seg = c & 7;
        int w   = sb + row * AT_STR + seg * 4;
        cpa16(s2u(sw + w + AT_KH), khh + (j0 + row) * DEPTH + seg * 8);
        cpa16(s2u(sw + w + AT_KL), khl + (j0 + row) * DEPTH + seg * 8);
        cpa16(s2u(sw + w + AT_VH), vth + (size_t)row * SEQ + j0 + seg * 8);
        cpa16(s2u(sw + w + AT_VL), vtl + (size_t)row * SEQ + j0 + seg * 8);
    }
#pragma unroll
    for (int it = 0; it < 2; it++) {
        int cc  = tid + it * 128;
        int row = cc >> 2;
        int seg = cc & 3;
        cpa16(s2u(sw + sb + AT_MASK + row * 16 + seg * 4),
              mb + (size_t)(i0 + row) * SEQ + j0 + seg * 16);
    }
    asm volatile("cp.async.commit_group;\n" ::: "memory");
}

__global__ __launch_bounds__(128) void attn_flash_tc(const unsigned char* __restrict__ mask)
{
    extern __shared__ uint32_t sw[];

    const int bh  = blockIdx.y;
    const int b_  = bh >> 4;
    const int hd  = bh & 15;
    const int qt  = gridDim.x - 1 - blockIdx.x;
    const int i0  = qt * 64;
    const int tid = threadIdx.x;
    const int lane = tid & 31;
    const int warp = tid >> 5;
    const int g    = lane >> 2;
    const int t4   = lane & 3;

    const int bgrp = lane >> 3;
    const int bRow = (lane & 7) + ((bgrp >> 1) ? 8 : 0);
    const int bK   = (bgrp & 1) * 8;

    const __nv_bfloat16* qhh = g_qhh + (size_t)bh * SEQ * DEPTH + (size_t)i0 * DEPTH;
    const __nv_bfloat16* qhl = g_qhl + (size_t)bh * SEQ * DEPTH + (size_t)i0 * DEPTH;
    const __nv_bfloat16* khh = g_khh + (size_t)bh * SEQ * DEPTH;
    const __nv_bfloat16* khl = g_khl + (size_t)bh * SEQ * DEPTH;
    const __nv_bfloat16* vth = g_vth + (size_t)bh * DEPTH * SEQ;
    const __nv_bfloat16* vtl = g_vtl + (size_t)bh * DEPTH * SEQ;
    const unsigned char* mb  = mask + (size_t)b_ * SEQ * SEQ;

    // Q tile (hi+lo)
#pragma unroll
    for (int it = 0; it < 4; it++) {
        int c   = tid + it * 128;
        int row = c >> 3;
        int seg = c & 7;
        int w   = row * AT_STR + seg * 4;
        cpa16(s2u(sw + AT_QH + w), qhh + row * DEPTH + seg * 8);
        cpa16(s2u(sw + AT_QL + w), qhl + row * DEPTH + seg * 8);
    }
    asm volatile("cp.async.commit_group;\n" ::: "memory");

    at_load_kv(sw, 0, khh, khl, vth, vtl, mb, i0, 0, tid);

    asm volatile("cp.async.wait_group 1;\n" ::: "memory");
    __syncthreads();

    // Q fragments via ldmatrix
    const uint32_t swb = s2u(sw);
    const int aRow = lane & 15;
    const int aK   = (lane >> 4) * 8;
    uint32_t qh[4][4], ql[4][4];
#pragma unroll
    for (int ks = 0; ks < 4; ks++) {
        uint32_t off = (uint32_t)(((warp * 16 + aRow) * AT_STR) * 4
                                  + (ks * 16 + aK) * 2);
        LDSM_X4(qh[ks][0], qh[ks][1], qh[ks][2], qh[ks][3], swb + AT_QH * 4 + off);
        LDSM_X4(ql[ks][0], ql[ks][1], ql[ks][2], ql[ks][3], swb + AT_QL * 4 + off);
    }

    float oc[8][4];
#pragma unroll
    for (int dt = 0; dt < 8; dt++)
#pragma unroll
        for (int c = 0; c < 4; c++) oc[dt][c] = 0.f;
    float m_a = -CUDART_INF_F, m_b = -CUDART_INF_F;
    float l_a = 0.f, l_b = 0.f;

    const int rA  = warp * 16 + g;
    const int rB  = rA + 8;
    const int iga = i0 + rA;
    const int igb = i0 + rB;
    const int ntiles = qt + 1;

    for (int t = 0; t < ntiles; t++) {
        const int j0 = t * 64;
        if (t + 1 < ntiles)
            at_load_kv(sw, ((t + 1) & 1) * AT_STAGE, khh, khl, vth, vtl,
                       mb, i0, (t + 1) * 64, tid);
        if (t + 1 < ntiles) asm volatile("cp.async.wait_group 1;\n" ::: "memory");
        else                asm volatile("cp.async.wait_group 0;\n" ::: "memory");
        __syncthreads();

        const uint32_t stb = swb + (uint32_t)((t & 1) * AT_STAGE) * 4;
        const uint32_t KHb = stb + AT_KH * 4;
        const uint32_t KLb = stb + AT_KL * 4;
        const uint32_t VHb = stb + AT_VH * 4;
        const uint32_t VLb = stb + AT_VL * 4;
        const unsigned char* Mt =
            (const unsigned char*)(sw + (t & 1) * AT_STAGE + AT_MASK);

        // S = Q K^T
        float sc[8][4];
#pragma unroll
        for (int nt = 0; nt < 8; nt++)
#pragma unroll
            for (int c = 0; c < 4; c++) sc[nt][c] = 0.f;
#pragma unroll
        for (int ks = 0; ks < 4; ks++) {
#pragma unroll
            for (int np = 0; np < 4; np++) {
                uint32_t off = (uint32_t)(((np * 16 + bRow) * AT_STR) * 4
                                          + (ks * 16 + bK) * 2);
                uint32_t h0, h1, h2, h3, l0, l1, l2, l3;
                LDSM_X4(h0, h1, h2, h3, KHb + off);
                LDSM_X4(l0, l1, l2, l3, KLb + off);
                uint32_t bhA[2] = {h0, h1}, bhB[2] = {h2, h3};
                uint32_t blA[2] = {l0, l1}, blB[2] = {l2, l3};
                MMA16816(sc[2*np],   qh[ks], bhA);
                MMA16816(sc[2*np],   qh[ks], blA);
                MMA16816(sc[2*np],   ql[ks], bhA);
                MMA16816(sc[2*np+1], qh[ks], bhB);
                MMA16816(sc[2*np+1], qh[ks], blB);
                MMA16816(sc[2*np+1], ql[ks], bhB);
            }
        }

        // scale + RPE + mask, row maxima
        float mxa = -CUDART_INF_F, mxb = -CUDART_INF_F;
#pragma unroll
        for (int nt = 0; nt < 8; nt++) {
#pragma unroll
            for (int cc = 0; cc < 2; cc++) {
                int jl = nt * 8 + 2 * t4 + cc;
                int jg = j0 + jl;
                float va = sc[nt][cc] * 0.125f + (float)(jg - iga);
                if (jg > iga || Mt[rA * 64 + jl]) va = -1e9f;
                sc[nt][cc] = va;
                mxa = fmaxf(mxa, va);
                float vb = sc[nt][cc + 2] * 0.125f + (float)(jg - igb);
                if (jg > igb || Mt[rB * 64 + jl]) vb = -1e9f;
                sc[nt][cc + 2] = vb;
                mxb = fmaxf(mxb, vb);
            }
        }
        mxa = fmaxf(mxa, __shfl_xor_sync(0xffffffffu, mxa, 1));
        mxa = fmaxf(mxa, __shfl_xor_sync(0xffffffffu, mxa, 2));
        mxb = fmaxf(mxb, __shfl_xor_sync(0xffffffffu, mxb, 1));
        mxb = fmaxf(mxb, __shfl_xor_sync(0xffffffffu, mxb, 2));

        float mna = fmaxf(m_a, mxa);
        float mnb = fmaxf(m_b, mxb);
        float ala = __expf(m_a - mna);
        float alb = __expf(m_b - mnb);
        m_a = mna; m_b = mnb;

        float sa = 0.f, sb2 = 0.f;
#pragma unroll
        for (int nt = 0; nt < 8; nt++) {
#pragma unroll
            for (int cc = 0; cc < 2; cc++) {
                float pa = __expf(sc[nt][cc] - mna);
                sc[nt][cc] = pa; sa += pa;
                float pb = __expf(sc[nt][cc + 2] - mnb);
                sc[nt][cc + 2] = pb; sb2 += pb;
            }
        }
        sa  += __shfl_xor_sync(0xffffffffu, sa, 1);
        sa  += __shfl_xor_sync(0xffffffffu, sa, 2);
        sb2 += __shfl_xor_sync(0xffffffffu, sb2, 1);
        sb2 += __shfl_xor_sync(0xffffffffu, sb2, 2);
        l_a = l_a * ala + sa;
        l_b = l_b * alb + sb2;

#pragma unroll
        for (int dt = 0; dt < 8; dt++) {
            oc[dt][0] *= ala; oc[dt][1] *= ala;
            oc[dt][2] *= alb; oc[dt][3] *= alb;
        }

        // P -> bf16-split A fragments
        uint32_t pah[4][4], pal[4][4];
#pragma unroll
        for (int kt = 0; kt < 4; kt++) {
            split2(sc[2*kt][0],   sc[2*kt][1],   pah[kt][0], pal[kt][0]);
            split2(sc[2*kt][2],   sc[2*kt][3],   pah[kt][1], pal[kt][1]);
            split2(sc[2*kt+1][0], sc[2*kt+1][1], pah[kt][2], pal[kt][2]);
            split2(sc[2*kt+1][2], sc[2*kt+1][3], pah[kt][3], pal[kt][3]);
        }

        // O += P V
#pragma unroll
        for (int kt = 0; kt < 4; kt++) {
#pragma unroll
            for (int dp = 0; dp < 4; dp++) {
                uint32_t off = (uint32_t)(((dp * 16 + bRow) * AT_STR) * 4
                                          + (kt * 16 + bK) * 2);
                uint32_t h0, h1, h2, h3, l0, l1, l2, l3;
                LDSM_X4(h0, h1, h2, h3, VHb + off);
                LDSM_X4(l0, l1, l2, l3, VLb + off);
                uint32_t vhA[2] = {h0, h1}, vhB[2] = {h2, h3};
                uint32_t vlA[2] = {l0, l1}, vlB[2] = {l2, l3};
                MMA16816(oc[2*dp],   pah[kt], vhA);
                MMA16816(oc[2*dp],   pah[kt], vlA);
                MMA16816(oc[2*dp],   pal[kt], vhA);
                MMA16816(oc[2*dp+1], pah[kt], vhB);
                MMA16816(oc[2*dp+1], pah[kt], vlB);
                MMA16816(oc[2*dp+1], pal[kt], vhB);
            }
        }
        __syncthreads();
    }

    // epilogue: normalize, write bf16-split ctx (GEMM A layout)
    float inva = 1.0f / l_a;
    float invb = 1.0f / l_b;
    const size_t rowA = (size_t)(b_ * SEQ + iga) * D_MODEL;
    const size_t rowB = (size_t)(b_ * SEQ + igb) * D_MODEL;
#pragma unroll
    for (int dt = 0; dt < 8; dt++) {
        int col = hd * 64 + dt * 8 + 2 * t4;
        uint32_t h0, l0;
        split2(oc[dt][0] * inva, oc[dt][1] * inva, h0, l0);
        *(uint32_t*)(g_ah + rowA + col) = h0;
        *(uint32_t*)(g_al + rowA + col) = l0;
        uint32_t h1, l1;
        split2(oc[dt][2] * invb, oc[dt][3] * invb, h1, l1);
        *(uint32_t*)(g_ah + rowB + col) = h1;
        *(uint32_t*)(g_al + rowB + col) = l1;
    }
    if (t4 == 0) {
        g_m[(size_t)bh * SEQ + iga] = m_a;
        g_l[(size_t)bh * SEQ + iga] = l_a;
        g_m[(size_t)bh * SEQ + igb] = m_b;
        g_l[(size_t)bh * SEQ + igb] = l_b;
    }
}

// ============================================================
// Optional full attention probabilities
// ============================================================
#define QS_STR 65

__global__ void attn_probs(const unsigned char* __restrict__ mask,
                           float* __restrict__ attn)
{
    __shared__ float Qs[64 * QS_STR];
    __shared__ float Ks[64 * QS_STR];
    __shared__ unsigned char Ms[64 * 64];

    const int bh = blockIdx.y;
    const int b_ = bh >> 4;
    const int qt = blockIdx.x;
    const int i0 = qt * 64;

    const int tid = threadIdx.x;
    const int tx  = tid & 15;
    const int ty  = tid >> 4;
    const int r0  = ty * 4;
    const int c0  = tx * 4;

    const __nv_bfloat16* qhh = g_qhh + (size_t)bh * SEQ * DEPTH;
    const __nv_bfloat16* qhl = g_qhl + (size_t)bh * SEQ * DEPTH;
    const __nv_bfloat16* khh = g_khh + (size_t)bh * SEQ * DEPTH;
    const __nv_bfloat16* khl = g_khl + (size_t)bh * SEQ * DEPTH;
    const unsigned char* mb  = mask + (size_t)b_ * SEQ * SEQ;

    for (int idx = tid; idx < 4096; idx += 256) {
        int r = idx >> 6;
        int c = idx & 63;
        size_t go = (size_t)(i0 + r) * DEPTH + c;
        Qs[r * QS_STR + c] = __bfloat162float(qhh[go]) + __bfloat162float(qhl[go]);
    }

    float mi[4], li[4];
#pragma unroll
    for (int i = 0; i < 4; i++) {
        mi[i] = g_m[(size_t)bh * SEQ + i0 + r0 + i];
        li[i] = 1.0f / g_l[(size_t)bh * SEQ + i0 + r0 + i];
    }
    __syncthreads();

    for (int jt = 0; jt < SEQ / 64; jt++) {
        const int j0 = jt * 64;
        if (j0 > i0 + 63) {
            for (int idx = tid; idx < 1024; idx += 256) {
                int r  = idx >> 4;
                int c4 = (idx & 15) << 2;
                float4 z = {0.f, 0.f, 0.f, 0.f};
                *(float4*)(attn + ((size_t)bh * SEQ + i0 + r) * SEQ + j0 + c4) = z;
            }
            continue;
        }
        for (int idx = tid; idx < 4096; idx += 256) {
            int r = idx >> 6;
            int c = idx & 63;
            size_t go = (size_t)(j0 + r) * DEPTH + c;
            Ks[r * QS_STR + c] = __bfloat162float(khh[go]) + __bfloat162float(khl[go]);
        }
        {
            int r   = tid >> 2;
            int c16 = (tid & 3) << 4;
            *(uint4*)(Ms + r * 64 + c16) =
                *(const uint4*)(mb + (size_t)(i0 + r) * SEQ + j0 + c16);
        }
        __syncthreads();

        float s[4][4];
#pragma unroll
        for (int i = 0; i < 4; i++)
#pragma unroll
            for (int j = 0; j < 4; j++) s[i][j] = 0.f;
#pragma unroll 16
        for (int k = 0; k < 64; k++) {
            float a[4], b[4];
#pragma unroll
            for (int i = 0; i < 4; i++) a[i] = Qs[(r0 + i) * QS_STR + k];
#pragma unroll
            for (int j = 0; j < 4; j++) b[j] = Ks[(c0 + j) * QS_STR + k];
#pragma unroll
            for (int i = 0; i < 4; i++)
#pragma unroll
                for (int j = 0; j < 4; j++)
                    s[i][j] += a[i] * b[j];
        }

#pragma unroll
        for (int i = 0; i < 4; i++) {
            int ig = i0 + r0 + i;
            float4 ov;
            float* pv = (float*)&ov;
#pragma unroll
            for (int j = 0; j < 4; j++) {
                int jg = j0 + c0 + j;
                float sv = s[i][j] * 0.125f + (float)(jg - ig);
                bool bad = (jg > ig) || Ms[(r0 + i) * 64 + (c0 + j)];
                pv[j] = bad ? 0.f : __expf(sv - mi[i]) * li[i];
            }
            *(float4*)(attn + ((size_t)bh * SEQ + ig) * SEQ + j0 + c0) = ov;
        }
        __syncthreads();
    }
}

// ============================================================
extern "C" void kernel_launch(void* const* d_in, const int* in_sizes, int n_in,
                              void* d_out, int out_size)
{
    const float* q  = (const float*)d_in[0];
    const float* k  = (const float*)d_in[1];
    const float* v  = (const float*)d_in[2];
    const float* Wq = (const float*)d_in[3];
    const float* bq = (const float*)d_in[4];
    const float* Wk = (const float*)d_in[5];
    const float* bk = (const float*)d_in[6];
    const float* Wv = (const float*)d_in[7];
    const float* bv = (const float*)d_in[8];
    const float* Wo = (const float*)d_in[9];
    const float* bo = (const float*)d_in[10];
    const unsigned char* mask = (const unsigned char*)d_in[11];

    float* out = (float*)d_out;
    const long long OUT_ELEMS = (long long)BATCH * SEQ * D_MODEL;
    const int writeAttn = ((long long)out_size > OUT_ELEMS) ? 1 : 0;
    float* attn_out = out + OUT_ELEMS;

    cudaFuncSetAttribute(gemm_mma,
                         cudaFuncAttributeMaxDynamicSharedMemorySize, GEMM_SMEM);
    cudaFuncSetAttribute(attn_flash_tc,
                         cudaFuncAttributeMaxDynamicSharedMemorySize, AT_SMEM);

    cvt_w4<<<dim3(32, 32, 4), 256>>>(Wq, Wk, Wv, Wo);
    cvt_x3<<<dim3(2048, 1, 3), 256>>>(q, k, v);

    // fused Q,K,V projections
    gemm_mma<<<dim3(8, 32, 3), 256, GEMM_SMEM>>>(bq, bk, bv, nullptr, 0);

    attn_flash_tc<<<dim3(SEQ / 64, BH), 128, AT_SMEM>>>(mask);

    if (writeAttn)
        attn_probs<<<dim3(SEQ / 64, BH), 256>>>(mask, attn_out);

    // output projection
    gemm_mma<<<dim3(8, 32, 1), 256, GEMM_SMEM>>>(bo, bo, bo, out, 3);
}